// round 7
// baseline (speedup 1.0000x reference)
#include <cuda_runtime.h>
#include <cuda_bf16.h>
#include <cstdint>

// FBGCN layer:
//   Hh = d_inv @ (lap @ (d_inv @ relu(x @ W_high)))  -- mma.sync bf16-split GEMMs
//   Hl = GCNConv(x, edge_index, W_conv, b_conv)
//   out = aL*Hl + aH*Hh

static constexpr int N_NODES = 4096;
static constexpr int DIM     = 256;
static constexpr int N_EDGES = 131072;

// fp32 scratch
__device__ __align__(16) float g_A[N_NODES * DIM];    // R / XW_conv
__device__ __align__(16) float g_P0[N_NODES * DIM];   // split-K partials
__device__ __align__(16) float g_P1[N_NODES * DIM];
__device__ __align__(16) float g_P2[N_NODES * DIM];
__device__ __align__(16) float g_P3[N_NODES * DIM];
__device__ float g_dis[N_NODES];
__device__ int   g_src[N_EDGES];
__device__ int   g_dst[N_EDGES];
__device__ int   g_is64;

// bf16 split buffers
__device__ __align__(128) __nv_bfloat16 g_dinv_hi[N_NODES * N_NODES];
__device__ __align__(128) __nv_bfloat16 g_dinv_lo[N_NODES * N_NODES];
__device__ __align__(128) __nv_bfloat16 g_lap_hi [N_NODES * N_NODES];
__device__ __align__(128) __nv_bfloat16 g_lap_lo [N_NODES * N_NODES];
__device__ __align__(128) __nv_bfloat16 g_Bhi[DIM * N_NODES];   // [256 x 4096] act^T
__device__ __align__(128) __nv_bfloat16 g_Blo[DIM * N_NODES];
__device__ __align__(128) __nv_bfloat16 g_xhi[N_NODES * DIM];   // x splits (K-major rows)
__device__ __align__(128) __nv_bfloat16 g_xlo[N_NODES * DIM];
__device__ __align__(128) __nv_bfloat16 g_Wth[DIM * DIM];       // W^T splits
__device__ __align__(128) __nv_bfloat16 g_Wtl[DIM * DIM];

// ---------------------------------------------------------------------------
// PTX helpers (baseline ISA only: cp.async, ldmatrix, mma.sync)
// ---------------------------------------------------------------------------
__device__ __forceinline__ uint32_t smem_u32(const void* p) {
    uint32_t a;
    asm("{ .reg .u64 t; cvta.to.shared.u64 t, %1; cvt.u32.u64 %0, t; }" : "=r"(a) : "l"(p));
    return a;
}
__device__ __forceinline__ void cp_async16(uint32_t dst, const void* src) {
    asm volatile("cp.async.cg.shared.global [%0], [%1], 16;" :: "r"(dst), "l"(src) : "memory");
}
__device__ __forceinline__ void cp_commit() { asm volatile("cp.async.commit_group;" ::: "memory"); }
template <int N>
__device__ __forceinline__ void cp_wait() { asm volatile("cp.async.wait_group %0;" :: "n"(N) : "memory"); }

__device__ __forceinline__ void ldsm_x4(uint32_t* r, uint32_t addr) {
    asm volatile("ldmatrix.sync.aligned.m8n8.x4.shared.b16 {%0,%1,%2,%3}, [%4];"
        : "=r"(r[0]), "=r"(r[1]), "=r"(r[2]), "=r"(r[3]) : "r"(addr));
}
__device__ __forceinline__ void mma16816(float* c, const uint32_t* a, const uint32_t* b) {
    asm volatile("mma.sync.aligned.m16n8k16.row.col.f32.bf16.bf16.f32 "
        "{%0,%1,%2,%3}, {%4,%5,%6,%7}, {%8,%9}, {%0,%1,%2,%3};"
        : "+f"(c[0]), "+f"(c[1]), "+f"(c[2]), "+f"(c[3])
        : "r"(a[0]), "r"(a[1]), "r"(a[2]), "r"(a[3]), "r"(b[0]), "r"(b[1]));
}

// ---------------------------------------------------------------------------
// Edge-index dtype detect + normalize
// ---------------------------------------------------------------------------
__global__ void detect_dtype_kernel(const unsigned int* __restrict__ raw)
{
    if (threadIdx.x == 0 && blockIdx.x == 0) {
        int is64 = 1;
        #pragma unroll 1
        for (int i = 0; i < 128; i++)
            if (raw[2 * i + 1] != 0u) { is64 = 0; break; }
        g_is64 = is64;
    }
}
__global__ void convert_edges_kernel(const void* __restrict__ rawp)
{
    int e = blockIdx.x * blockDim.x + threadIdx.x;
    if (e >= N_EDGES) return;
    if (g_is64) {
        const long long* ei = (const long long*)rawp;
        g_src[e] = (int)ei[e];
        g_dst[e] = (int)ei[N_EDGES + e];
    } else {
        const int* ei = (const int*)rawp;
        g_src[e] = ei[e];
        g_dst[e] = ei[N_EDGES + e];
    }
}

// ---------------------------------------------------------------------------
// fp32 -> (hi, lo) bf16 split, same layout
// ---------------------------------------------------------------------------
__global__ void split_kernel(const float4* __restrict__ src,
                             uint2* __restrict__ hi, uint2* __restrict__ lo, int n4)
{
    int id = blockIdx.x * blockDim.x + threadIdx.x;
    if (id >= n4) return;
    float4 v = src[id];
    __nv_bfloat16 hx = __float2bfloat16(v.x), hy = __float2bfloat16(v.y);
    __nv_bfloat16 hz = __float2bfloat16(v.z), hw = __float2bfloat16(v.w);
    __nv_bfloat16 lx = __float2bfloat16(v.x - __bfloat162float(hx));
    __nv_bfloat16 ly = __float2bfloat16(v.y - __bfloat162float(hy));
    __nv_bfloat16 lz = __float2bfloat16(v.z - __bfloat162float(hz));
    __nv_bfloat16 lw = __float2bfloat16(v.w - __bfloat162float(hw));
    __nv_bfloat162 h01(hx, hy), h23(hz, hw), l01(lx, ly), l23(lz, lw);
    uint2 H, L;
    H.x = *(uint32_t*)&h01; H.y = *(uint32_t*)&h23;
    L.x = *(uint32_t*)&l01; L.y = *(uint32_t*)&l23;
    hi[id] = H; lo[id] = L;
}

// ---------------------------------------------------------------------------
// activations: fp32 [4096 x 256] (sum of NSUM buffers) -> bf16 splits [256 x 4096]
// ---------------------------------------------------------------------------
template <int NSUM>
__global__ void transpose_split_kernel(const float* __restrict__ s0,
                                       const float* __restrict__ s1,
                                       const float* __restrict__ s2,
                                       const float* __restrict__ s3,
                                       __nv_bfloat16* __restrict__ hi,
                                       __nv_bfloat16* __restrict__ lo)
{
    __shared__ float tile[32][33];
    int k0 = blockIdx.x * 32;
    int n0 = blockIdx.y * 32;
    int tx = threadIdx.x, ty = threadIdx.y;    // 32 x 8
    #pragma unroll
    for (int j = 0; j < 4; j++) {
        size_t o = (size_t)(k0 + ty + j * 8) * DIM + n0 + tx;
        float v = s0[o];
        if (NSUM > 1) v += s1[o];
        if (NSUM > 2) v += s2[o];
        if (NSUM > 3) v += s3[o];
        tile[ty + j * 8][tx] = v;
    }
    __syncthreads();
    #pragma unroll
    for (int j = 0; j < 4; j++) {
        int n = ty + j * 8;
        float v = tile[tx][n];
        __nv_bfloat16 h = __float2bfloat16(v);
        __nv_bfloat16 l = __float2bfloat16(v - __bfloat162float(h));
        size_t o = (size_t)(n0 + n) * N_NODES + k0 + tx;
        hi[o] = h; lo[o] = l;
    }
}

// W [256 x 256] fp32 row-major -> W^T bf16 splits [256 x 256]
__global__ void wtranspose_split_kernel(const float* __restrict__ W,
                                        __nv_bfloat16* __restrict__ hi,
                                        __nv_bfloat16* __restrict__ lo)
{
    __shared__ float tile[32][33];
    int k0 = blockIdx.x * 32;
    int n0 = blockIdx.y * 32;
    int tx = threadIdx.x, ty = threadIdx.y;    // 32 x 8
    #pragma unroll
    for (int j = 0; j < 4; j++)
        tile[ty + j * 8][tx] = W[(size_t)(k0 + ty + j * 8) * DIM + n0 + tx];
    __syncthreads();
    #pragma unroll
    for (int j = 0; j < 4; j++) {
        int n = ty + j * 8;
        float v = tile[tx][n];
        __nv_bfloat16 h = __float2bfloat16(v);
        __nv_bfloat16 l = __float2bfloat16(v - __bfloat162float(h));
        size_t o = (size_t)(n0 + n) * DIM + k0 + tx;
        hi[o] = h; lo[o] = l;
    }
}

// ---------------------------------------------------------------------------
// mma.sync GEMM: C[4096 x 256] f32, 3-term bf16 split, split-K via blockIdx.z.
// CTA tile 128(M) x 256(N), BK=64, 512 threads / 16 warps (4m x 4n), warp 32x64.
// ROWB=144: cp.async writes and ldmatrix reads both bank-conflict-free.
// 2-stage cp.async double buffer (prefetch distance 2 iters).
// ---------------------------------------------------------------------------
static constexpr int ROWB     = 144;                  // 128B data + 16B pad
static constexpr int A_BYTES  = 128 * ROWB;           // 18432
static constexpr int B_BYTES  = 256 * ROWB;           // 36864
static constexpr int STAGE_B  = A_BYTES + B_BYTES;    // 55296
static constexpr int GEMM_SMEM = 2 * STAGE_B;         // 110592

template <bool RELU>
__global__ __launch_bounds__(512, 1) void gemm_mma_kernel(
    const __nv_bfloat16* __restrict__ Ahi, const __nv_bfloat16* __restrict__ Alo,
    const __nv_bfloat16* __restrict__ Bhi, const __nv_bfloat16* __restrict__ Blo,
    float* __restrict__ C0, float* __restrict__ C1,
    float* __restrict__ C2, float* __restrict__ C3,
    int strideA, int strideB, int nit, int segShift)
{
    extern __shared__ char smem[];
    const uint32_t sbase = smem_u32(smem);
    const int t    = threadIdx.x;
    const int lane = t & 31;
    const int wid  = t >> 5;
    const int wm   = wid >> 2;       // 0..3 -> M offset wm*32
    const int wn   = wid & 3;        // 0..3 -> N offset wn*64
    const int m0   = blockIdx.y * 128;
    const int n0   = blockIdx.x * 256;
    const int cBeg = blockIdx.z * nit;
    const int segMask = (1 << segShift) - 1;

    const __nv_bfloat16* Aseg[3] = { Ahi, Ahi, Alo };
    const __nv_bfloat16* Bseg[3] = { Bhi, Blo, Bhi };

    // cp.async task mapping: 6 tasks/thread (2 A rows + 4 B rows), ch = t&7
    const int rowBase = t >> 3;          // 0..63
    const int ch      = t & 7;
    uint32_t aOffG[2], sOffA[2], bOffG[4], sOffB[4];
    #pragma unroll
    for (int i = 0; i < 2; i++) {
        int row = rowBase + 64 * i;
        aOffG[i] = (uint32_t)((m0 + row) * strideA + ch * 8);
        sOffA[i] = (uint32_t)(row * ROWB + ch * 16);
    }
    #pragma unroll
    for (int i = 0; i < 4; i++) {
        int row = rowBase + 64 * i;
        bOffG[i] = (uint32_t)((n0 + row) * strideB + ch * 8);
        sOffB[i] = (uint32_t)(A_BYTES + row * ROWB + ch * 16);
    }

    // ldmatrix lane bases (byte offsets within stage)
    const uint32_t aLd = (uint32_t)(wm * 32 + (lane & 15)) * ROWB + (lane >> 4) * 16;
    const uint32_t bLd = A_BYTES +
        (uint32_t)(wn * 64 + ((lane >> 4) & 1) * 8 + (lane & 7)) * ROWB + ((lane >> 3) & 1) * 16;

    float acc[2][8][4];
    #pragma unroll
    for (int f = 0; f < 2; f++)
        #pragma unroll
        for (int j = 0; j < 8; j++)
            #pragma unroll
            for (int e = 0; e < 4; e++) acc[f][j][e] = 0.f;

    auto load_stage = [&](int ci, int s) {
        if (ci < nit) {
            int c   = cBeg + ci;
            int seg = c >> segShift;
            int k0  = (c & segMask) << 6;
            const __nv_bfloat16* ap = Aseg[seg] + k0;
            const __nv_bfloat16* bp = Bseg[seg] + k0;
            uint32_t sb = sbase + s * STAGE_B;
            #pragma unroll
            for (int i = 0; i < 2; i++) cp_async16(sb + sOffA[i], ap + aOffG[i]);
            #pragma unroll
            for (int i = 0; i < 4; i++) cp_async16(sb + sOffB[i], bp + bOffG[i]);
        }
        cp_commit();
    };

    load_stage(0, 0);
    load_stage(1, 1);

    for (int ci = 0; ci < nit; ci++) {
        cp_wait<1>();
        __syncthreads();

        uint32_t sb = sbase + (ci & 1) * STAGE_B;
        #pragma unroll
        for (int ks = 0; ks < 4; ks++) {
            uint32_t a[2][4], b[4][4];
            #pragma unroll
            for (int f = 0; f < 2; f++)
                ldsm_x4(a[f], sb + aLd + f * 16 * ROWB + ks * 32);
            #pragma unroll
            for (int j = 0; j < 4; j++)
                ldsm_x4(b[j], sb + bLd + j * 16 * ROWB + ks * 32);
            #pragma unroll
            for (int f = 0; f < 2; f++)
                #pragma unroll
                for (int j = 0; j < 4; j++) {
                    mma16816(acc[f][2 * j + 0], a[f], &b[j][0]);
                    mma16816(acc[f][2 * j + 1], a[f], &b[j][2]);
                }
        }
        __syncthreads();
        load_stage(ci + 2, ci & 1);
    }

    float* C = (blockIdx.z == 0) ? C0 : (blockIdx.z == 1) ? C1
             : (blockIdx.z == 2) ? C2 : C3;
    const int gid = lane >> 2;
    const int tig = lane & 3;
    #pragma unroll
    for (int f = 0; f < 2; f++) {
        int rbase = m0 + wm * 32 + f * 16 + gid;
        #pragma unroll
        for (int j = 0; j < 8; j++) {
            int col = n0 + wn * 64 + j * 8 + tig * 2;
            float2 v0 = { acc[f][j][0], acc[f][j][1] };
            float2 v1 = { acc[f][j][2], acc[f][j][3] };
            if (RELU) {
                v0.x = fmaxf(v0.x, 0.f); v0.y = fmaxf(v0.y, 0.f);
                v1.x = fmaxf(v1.x, 0.f); v1.y = fmaxf(v1.y, 0.f);
            }
            *reinterpret_cast<float2*>(C + (size_t)rbase * DIM + col) = v0;
            *reinterpret_cast<float2*>(C + (size_t)(rbase + 8) * DIM + col) = v1;
        }
    }
}

// ---------------------------------------------------------------------------
// GCN branch
// ---------------------------------------------------------------------------
__global__ void deg_init_kernel()
{
    int i = blockIdx.x * blockDim.x + threadIdx.x;
    if (i < N_NODES) g_dis[i] = 1.0f;
}
__global__ void deg_count_kernel()
{
    int e = blockIdx.x * blockDim.x + threadIdx.x;
    if (e < N_EDGES) atomicAdd(&g_dis[g_dst[e]], 1.0f);
}
__global__ void deg_finalize_kernel()
{
    int i = blockIdx.x * blockDim.x + threadIdx.x;
    if (i < N_NODES) g_dis[i] = rsqrtf(g_dis[i]);
}
__global__ void selfloop_init_kernel(float* __restrict__ out)
{
    int id = blockIdx.x * blockDim.x + threadIdx.x;
    if (id < N_NODES * DIM / 4) {
        int row = id / (DIM / 4);
        float s = g_dis[row]; s = s * s;
        float4 v = reinterpret_cast<const float4*>(g_A)[id];
        v.x *= s; v.y *= s; v.z *= s; v.w *= s;
        reinterpret_cast<float4*>(out)[id] = v;
    }
}
__global__ void scatter_kernel(float* __restrict__ out)
{
    int id = blockIdx.x * blockDim.x + threadIdx.x;
    if (id >= N_EDGES * (DIM / 4)) return;
    int e   = id >> 6;
    int col = (id & 63) << 2;
    int src = g_src[e];
    int dst = g_dst[e];
    float norm = g_dis[src] * g_dis[dst];
    float4 v = *reinterpret_cast<const float4*>(g_A + (size_t)src * DIM + col);
    float* o = out + (size_t)dst * DIM + col;
    atomicAdd(o + 0, v.x * norm);
    atomicAdd(o + 1, v.y * norm);
    atomicAdd(o + 2, v.z * norm);
    atomicAdd(o + 3, v.w * norm);
}
__global__ void combine_kernel(float* __restrict__ out,
                               const float* __restrict__ b,
                               const float* __restrict__ aLp,
                               const float* __restrict__ aHp)
{
    int id = blockIdx.x * blockDim.x + threadIdx.x;
    if (id >= N_NODES * DIM / 4) return;
    float aL = aLp[0], aH = aHp[0];
    int c4 = (id & (DIM / 4 - 1)) << 2;
    float4 hl = reinterpret_cast<const float4*>(out)[id];
    float4 h0 = reinterpret_cast<const float4*>(g_P0)[id];
    float4 h1 = reinterpret_cast<const float4*>(g_P1)[id];
    float4 h2 = reinterpret_cast<const float4*>(g_P2)[id];
    float4 h3 = reinterpret_cast<const float4*>(g_P3)[id];
    float4 bb = *reinterpret_cast<const float4*>(b + c4);
    float4 r;
    r.x = aL * (hl.x + bb.x) + aH * ((h0.x + h1.x) + (h2.x + h3.x));
    r.y = aL * (hl.y + bb.y) + aH * ((h0.y + h1.y) + (h2.y + h3.y));
    r.z = aL * (hl.z + bb.z) + aH * ((h0.z + h1.z) + (h2.z + h3.z));
    r.w = aL * (hl.w + bb.w) + aH * ((h0.w + h1.w) + (h2.w + h3.w));
    reinterpret_cast<float4*>(out)[id] = r;
}

// ---------------------------------------------------------------------------
extern "C" void kernel_launch(void* const* d_in, const int* in_sizes, int n_in,
                              void* d_out, int out_size)
{
    const float* x      = (const float*)d_in[0];
    const void*  ei_raw = d_in[1];
    const float* lap    = (const float*)d_in[2];
    const float* d_inv  = (const float*)d_in[3];
    const float* W_high = (const float*)d_in[4];
    const float* W_conv = (const float*)d_in[5];
    const float* b_conv = (const float*)d_in[6];
    const float* aL     = (const float*)d_in[7];
    const float* aH     = (const float*)d_in[8];
    float*       out    = (float*)d_out;

    float *pA, *pP0, *pP1, *pP2, *pP3;
    cudaGetSymbolAddress((void**)&pA,  g_A);
    cudaGetSymbolAddress((void**)&pP0, g_P0);
    cudaGetSymbolAddress((void**)&pP1, g_P1);
    cudaGetSymbolAddress((void**)&pP2, g_P2);
    cudaGetSymbolAddress((void**)&pP3, g_P3);
    __nv_bfloat16 *pDh, *pDl, *pLh, *pLl, *pBh, *pBl, *pXh, *pXl, *pWh, *pWl;
    cudaGetSymbolAddress((void**)&pDh, g_dinv_hi);
    cudaGetSymbolAddress((void**)&pDl, g_dinv_lo);
    cudaGetSymbolAddress((void**)&pLh, g_lap_hi);
    cudaGetSymbolAddress((void**)&pLl, g_lap_lo);
    cudaGetSymbolAddress((void**)&pBh, g_Bhi);
    cudaGetSymbolAddress((void**)&pBl, g_Blo);
    cudaGetSymbolAddress((void**)&pXh, g_xhi);
    cudaGetSymbolAddress((void**)&pXl, g_xlo);
    cudaGetSymbolAddress((void**)&pWh, g_Wth);
    cudaGetSymbolAddress((void**)&pWl, g_Wtl);

    cudaFuncSetAttribute(gemm_mma_kernel<false>, cudaFuncAttributeMaxDynamicSharedMemorySize, GEMM_SMEM);
    cudaFuncSetAttribute(gemm_mma_kernel<true >, cudaFuncAttributeMaxDynamicSharedMemorySize, GEMM_SMEM);

    // Edge normalization
    detect_dtype_kernel <<<1, 32>>>((const unsigned int*)ei_raw);
    convert_edges_kernel<<<N_EDGES / 256, 256>>>(ei_raw);

    // Splits of inputs
    int nbig4 = N_NODES * N_NODES / 4;
    split_kernel<<<nbig4 / 256, 256>>>((const float4*)d_inv, (uint2*)pDh, (uint2*)pDl, nbig4);
    split_kernel<<<nbig4 / 256, 256>>>((const float4*)lap,   (uint2*)pLh, (uint2*)pLl, nbig4);
    int nx4 = N_NODES * DIM / 4;
    split_kernel<<<nx4 / 256, 256>>>((const float4*)x, (uint2*)pXh, (uint2*)pXl, nx4);

    dim3 gBig(1, N_NODES / 128, 4);          // (1, 32, 4) = 128 CTAs
    dim3 gSm (1, N_NODES / 128, 1);          // (1, 32, 1)
    dim3 gTr(N_NODES / 32, DIM / 32);
    dim3 bTr(32, 8);
    dim3 gWt(DIM / 32, DIM / 32);
    const int NIT_BIG = (3 * N_NODES / 64) / 4;   // 48 per z
    const int NIT_SM  = 3 * DIM / 64;             // 12
    const int SEG_BIG = 6;                        // 64 iters / segment
    const int SEG_SM  = 2;                        // 4 iters / segment

    // R = relu(x @ W_high)
    wtranspose_split_kernel<<<gWt, bTr>>>(W_high, pWh, pWl);
    gemm_mma_kernel<true><<<gSm, 512, GEMM_SMEM>>>(pXh, pXl, pWh, pWl,
        pA, pA, pA, pA, DIM, DIM, NIT_SM, SEG_SM);
    transpose_split_kernel<1><<<gTr, bTr>>>(pA, nullptr, nullptr, nullptr, pBh, pBl);
    // T1 = d_inv @ R
    gemm_mma_kernel<false><<<gBig, 512, GEMM_SMEM>>>(pDh, pDl, pBh, pBl,
        pP0, pP1, pP2, pP3, N_NODES, N_NODES, NIT_BIG, SEG_BIG);
    // XW_conv = x @ W_conv (into g_A)
    wtranspose_split_kernel<<<gWt, bTr>>>(W_conv, pWh, pWl);
    gemm_mma_kernel<false><<<gSm, 512, GEMM_SMEM>>>(pXh, pXl, pWh, pWl,
        pA, pA, pA, pA, DIM, DIM, NIT_SM, SEG_SM);
    // T2 = lap @ T1
    transpose_split_kernel<4><<<gTr, bTr>>>(pP0, pP1, pP2, pP3, pBh, pBl);
    gemm_mma_kernel<false><<<gBig, 512, GEMM_SMEM>>>(pLh, pLl, pBh, pBl,
        pP0, pP1, pP2, pP3, N_NODES, N_NODES, NIT_BIG, SEG_BIG);
    // Hh = d_inv @ T2 (parts stay in P0..P3)
    transpose_split_kernel<4><<<gTr, bTr>>>(pP0, pP1, pP2, pP3, pBh, pBl);
    gemm_mma_kernel<false><<<gBig, 512, GEMM_SMEM>>>(pDh, pDl, pBh, pBl,
        pP0, pP1, pP2, pP3, N_NODES, N_NODES, NIT_BIG, SEG_BIG);

    // GCN branch
    deg_init_kernel    <<<N_NODES / 256, 256>>>();
    deg_count_kernel   <<<N_EDGES / 256, 256>>>();
    deg_finalize_kernel<<<N_NODES / 256, 256>>>();
    int nvec = N_NODES * DIM / 4;
    selfloop_init_kernel<<<(nvec + 255) / 256, 256>>>(out);
    int nscat = N_EDGES * (DIM / 4);
    scatter_kernel<<<(nscat + 255) / 256, 256>>>(out);
    combine_kernel<<<(nvec + 255) / 256, 256>>>(out, b_conv, aL, aH);
}

// round 8
// speedup vs baseline: 1.2356x; 1.2356x over previous
#include <cuda_runtime.h>
#include <cuda_bf16.h>
#include <cstdint>

// FBGCN layer:
//   Hh = d_inv @ (lap @ (d_inv @ relu(x @ W_high)))  -- mma.sync bf16-split GEMMs
//   Hl = GCNConv(x, edge_index, W_conv, b_conv)      -- CSR gather (no fp atomics)
//   out = aL*Hl + aH*Hh

static constexpr int N_NODES = 4096;
static constexpr int DIM     = 256;
static constexpr int N_EDGES = 131072;

// fp32 scratch
__device__ __align__(16) float g_A[N_NODES * DIM];    // R / XW_conv
__device__ __align__(16) float g_P0[N_NODES * DIM];   // split-K partials
__device__ __align__(16) float g_P1[N_NODES * DIM];
__device__ __align__(16) float g_P2[N_NODES * DIM];
__device__ __align__(16) float g_P3[N_NODES * DIM];
__device__ float g_dis[N_NODES];
__device__ int   g_src[N_EDGES];
__device__ int   g_dst[N_EDGES];
__device__ int   g_is64;
// CSR
__device__ int   g_degi[N_NODES];
__device__ int   g_rowoff[N_NODES + 1];
__device__ int   g_cursor[N_NODES];
__device__ int   g_csr[N_EDGES];

// bf16 split buffers
__device__ __align__(128) __nv_bfloat16 g_dinv_hi[N_NODES * N_NODES];
__device__ __align__(128) __nv_bfloat16 g_dinv_lo[N_NODES * N_NODES];
__device__ __align__(128) __nv_bfloat16 g_lap_hi [N_NODES * N_NODES];
__device__ __align__(128) __nv_bfloat16 g_lap_lo [N_NODES * N_NODES];
__device__ __align__(128) __nv_bfloat16 g_Bhi[DIM * N_NODES];   // [256 x 4096] act^T
__device__ __align__(128) __nv_bfloat16 g_Blo[DIM * N_NODES];
__device__ __align__(128) __nv_bfloat16 g_xhi[N_NODES * DIM];   // x splits (K-major rows)
__device__ __align__(128) __nv_bfloat16 g_xlo[N_NODES * DIM];
__device__ __align__(128) __nv_bfloat16 g_Wth[DIM * DIM];       // W^T splits
__device__ __align__(128) __nv_bfloat16 g_Wtl[DIM * DIM];

// ---------------------------------------------------------------------------
// PTX helpers (baseline ISA only: cp.async, ldmatrix, mma.sync)
// ---------------------------------------------------------------------------
__device__ __forceinline__ uint32_t smem_u32(const void* p) {
    uint32_t a;
    asm("{ .reg .u64 t; cvta.to.shared.u64 t, %1; cvt.u32.u64 %0, t; }" : "=r"(a) : "l"(p));
    return a;
}
__device__ __forceinline__ void cp_async16(uint32_t dst, const void* src) {
    asm volatile("cp.async.cg.shared.global [%0], [%1], 16;" :: "r"(dst), "l"(src) : "memory");
}
__device__ __forceinline__ void cp_commit() { asm volatile("cp.async.commit_group;" ::: "memory"); }
template <int N>
__device__ __forceinline__ void cp_wait() { asm volatile("cp.async.wait_group %0;" :: "n"(N) : "memory"); }

__device__ __forceinline__ void ldsm_x4(uint32_t* r, uint32_t addr) {
    asm volatile("ldmatrix.sync.aligned.m8n8.x4.shared.b16 {%0,%1,%2,%3}, [%4];"
        : "=r"(r[0]), "=r"(r[1]), "=r"(r[2]), "=r"(r[3]) : "r"(addr));
}
__device__ __forceinline__ void mma16816(float* c, const uint32_t* a, const uint32_t* b) {
    asm volatile("mma.sync.aligned.m16n8k16.row.col.f32.bf16.bf16.f32 "
        "{%0,%1,%2,%3}, {%4,%5,%6,%7}, {%8,%9}, {%0,%1,%2,%3};"
        : "+f"(c[0]), "+f"(c[1]), "+f"(c[2]), "+f"(c[3])
        : "r"(a[0]), "r"(a[1]), "r"(a[2]), "r"(a[3]), "r"(b[0]), "r"(b[1]));
}

// ---------------------------------------------------------------------------
// Edge-index dtype detect + normalize
// ---------------------------------------------------------------------------
__global__ void detect_dtype_kernel(const unsigned int* __restrict__ raw)
{
    if (threadIdx.x == 0 && blockIdx.x == 0) {
        int is64 = 1;
        #pragma unroll 1
        for (int i = 0; i < 128; i++)
            if (raw[2 * i + 1] != 0u) { is64 = 0; break; }
        g_is64 = is64;
    }
}
__global__ void convert_edges_kernel(const void* __restrict__ rawp)
{
    int e = blockIdx.x * blockDim.x + threadIdx.x;
    if (e >= N_EDGES) return;
    if (g_is64) {
        const long long* ei = (const long long*)rawp;
        g_src[e] = (int)ei[e];
        g_dst[e] = (int)ei[N_EDGES + e];
    } else {
        const int* ei = (const int*)rawp;
        g_src[e] = ei[e];
        g_dst[e] = ei[N_EDGES + e];
    }
}

// ---------------------------------------------------------------------------
// fp32 -> (hi, lo) bf16 split, 8 elements per thread, uint4 stores
// ---------------------------------------------------------------------------
__global__ void split_kernel(const float4* __restrict__ src,
                             uint4* __restrict__ hi, uint4* __restrict__ lo, int n8)
{
    int id = blockIdx.x * blockDim.x + threadIdx.x;
    if (id >= n8) return;
    float4 a = src[2 * id], b = src[2 * id + 1];
    float f[8] = { a.x, a.y, a.z, a.w, b.x, b.y, b.z, b.w };
    uint32_t H[4], L[4];
    #pragma unroll
    for (int i = 0; i < 4; i++) {
        __nv_bfloat16 h0 = __float2bfloat16(f[2 * i + 0]);
        __nv_bfloat16 h1 = __float2bfloat16(f[2 * i + 1]);
        __nv_bfloat16 l0 = __float2bfloat16(f[2 * i + 0] - __bfloat162float(h0));
        __nv_bfloat16 l1 = __float2bfloat16(f[2 * i + 1] - __bfloat162float(h1));
        __nv_bfloat162 hh(h0, h1), ll(l0, l1);
        H[i] = *(uint32_t*)&hh;
        L[i] = *(uint32_t*)&ll;
    }
    hi[id] = make_uint4(H[0], H[1], H[2], H[3]);
    lo[id] = make_uint4(L[0], L[1], L[2], L[3]);
}

// ---------------------------------------------------------------------------
// activations: fp32 [4096 x 256] (sum of NSUM buffers) -> bf16 splits [256 x 4096]
// ---------------------------------------------------------------------------
template <int NSUM>
__global__ void transpose_split_kernel(const float* __restrict__ s0,
                                       const float* __restrict__ s1,
                                       const float* __restrict__ s2,
                                       const float* __restrict__ s3,
                                       __nv_bfloat16* __restrict__ hi,
                                       __nv_bfloat16* __restrict__ lo)
{
    __shared__ float tile[32][33];
    int k0 = blockIdx.x * 32;
    int n0 = blockIdx.y * 32;
    int tx = threadIdx.x, ty = threadIdx.y;    // 32 x 8
    #pragma unroll
    for (int j = 0; j < 4; j++) {
        size_t o = (size_t)(k0 + ty + j * 8) * DIM + n0 + tx;
        float v = s0[o];
        if (NSUM > 1) v += s1[o];
        if (NSUM > 2) v += s2[o];
        if (NSUM > 3) v += s3[o];
        tile[ty + j * 8][tx] = v;
    }
    __syncthreads();
    #pragma unroll
    for (int j = 0; j < 4; j++) {
        int n = ty + j * 8;
        float v = tile[tx][n];
        __nv_bfloat16 h = __float2bfloat16(v);
        __nv_bfloat16 l = __float2bfloat16(v - __bfloat162float(h));
        size_t o = (size_t)(n0 + n) * N_NODES + k0 + tx;
        hi[o] = h; lo[o] = l;
    }
}

// W [256 x 256] fp32 row-major -> W^T bf16 splits [256 x 256]
__global__ void wtranspose_split_kernel(const float* __restrict__ W,
                                        __nv_bfloat16* __restrict__ hi,
                                        __nv_bfloat16* __restrict__ lo)
{
    __shared__ float tile[32][33];
    int k0 = blockIdx.x * 32;
    int n0 = blockIdx.y * 32;
    int tx = threadIdx.x, ty = threadIdx.y;    // 32 x 8
    #pragma unroll
    for (int j = 0; j < 4; j++)
        tile[ty + j * 8][tx] = W[(size_t)(k0 + ty + j * 8) * DIM + n0 + tx];
    __syncthreads();
    #pragma unroll
    for (int j = 0; j < 4; j++) {
        int n = ty + j * 8;
        float v = tile[tx][n];
        __nv_bfloat16 h = __float2bfloat16(v);
        __nv_bfloat16 l = __float2bfloat16(v - __bfloat162float(h));
        size_t o = (size_t)(n0 + n) * DIM + k0 + tx;
        hi[o] = h; lo[o] = l;
    }
}

// ---------------------------------------------------------------------------
// mma.sync GEMM (R6 config): C[4096 x 256] f32, 3-term bf16 split, split-K.
// CTA tile 128(M) x 128(N), BK=64, 256 threads / 8 warps (2m x 4n), warp 64x32.
// ROWB=144: cp.async writes and ldmatrix reads both bank-conflict-free.
// 3-stage cp.async pipeline, 2 CTAs/SM. blockIdx.z selects K chunk -> partial.
// ---------------------------------------------------------------------------
static constexpr int STAGES   = 3;
static constexpr int ROWB     = 144;                  // 128B data + 16B pad
static constexpr int A_BYTES  = 128 * ROWB;           // 18432
static constexpr int STAGE_B  = 2 * A_BYTES;          // 36864
static constexpr int GEMM_SMEM = STAGES * STAGE_B;    // 110592

template <bool RELU>
__global__ __launch_bounds__(256, 2) void gemm_mma_kernel(
    const __nv_bfloat16* __restrict__ Ahi, const __nv_bfloat16* __restrict__ Alo,
    const __nv_bfloat16* __restrict__ Bhi, const __nv_bfloat16* __restrict__ Blo,
    float* __restrict__ C0, float* __restrict__ C1,
    float* __restrict__ C2, float* __restrict__ C3,
    int strideA, int strideB, int nit, int segShift)
{
    extern __shared__ char smem[];
    const uint32_t sbase = smem_u32(smem);
    const int t    = threadIdx.x;
    const int lane = t & 31;
    const int wid  = t >> 5;
    const int wm   = wid >> 2;       // 0..1 -> M offset wm*64
    const int wn   = wid & 3;        // 0..3 -> N offset wn*32
    const int m0   = blockIdx.y * 128;
    const int n0   = blockIdx.x * 128;
    const int cBeg = blockIdx.z * nit;
    const int segMask = (1 << segShift) - 1;

    const __nv_bfloat16* Aseg[3] = { Ahi, Ahi, Alo };
    const __nv_bfloat16* Bseg[3] = { Bhi, Blo, Bhi };

    // cp.async task mapping: 8 tasks/thread (4 A rows + 4 B rows), ch = t&7
    const int rowBase = t >> 3;          // 0..31
    const int ch      = t & 7;
    uint32_t aOffG[4], bOffG[4], sOffA[4];
    #pragma unroll
    for (int i = 0; i < 4; i++) {
        int row = rowBase + 32 * i;
        aOffG[i] = (uint32_t)((m0 + row) * strideA + ch * 8);
        bOffG[i] = (uint32_t)((n0 + row) * strideB + ch * 8);
        sOffA[i] = (uint32_t)(row * ROWB + ch * 16);
    }

    // ldmatrix lane bases (byte offsets within stage)
    const uint32_t aLd = (uint32_t)(wm * 64 + (lane & 15)) * ROWB + (lane >> 4) * 16;
    const uint32_t bLd = A_BYTES +
        (uint32_t)(wn * 32 + ((lane >> 4) & 1) * 8 + (lane & 7)) * ROWB + ((lane >> 3) & 1) * 16;

    float acc[4][4][4];
    #pragma unroll
    for (int f = 0; f < 4; f++)
        #pragma unroll
        for (int j = 0; j < 4; j++)
            #pragma unroll
            for (int e = 0; e < 4; e++) acc[f][j][e] = 0.f;

    auto load_stage = [&](int ci, int s) {
        if (ci < nit) {
            int c   = cBeg + ci;
            int seg = c >> segShift;
            int k0  = (c & segMask) << 6;
            const __nv_bfloat16* ap = Aseg[seg] + k0;
            const __nv_bfloat16* bp = Bseg[seg] + k0;
            uint32_t sb = sbase + s * STAGE_B;
            #pragma unroll
            for (int i = 0; i < 4; i++) cp_async16(sb + sOffA[i], ap + aOffG[i]);
            #pragma unroll
            for (int i = 0; i < 4; i++) cp_async16(sb + A_BYTES + sOffA[i], bp + bOffG[i]);
        }
        cp_commit();
    };

    load_stage(0, 0);
    load_stage(1, 1);

    for (int ci = 0; ci < nit; ci++) {
        cp_wait<STAGES - 2>();
        __syncthreads();
        load_stage(ci + STAGES - 1, (ci + STAGES - 1) % STAGES);

        uint32_t sb = sbase + (ci % STAGES) * STAGE_B;
        #pragma unroll
        for (int ks = 0; ks < 4; ks++) {
            uint32_t a[4][4], b[2][4];
            #pragma unroll
            for (int f = 0; f < 4; f++)
                ldsm_x4(a[f], sb + aLd + f * 16 * ROWB + ks * 32);
            ldsm_x4(b[0], sb + bLd + ks * 32);
            ldsm_x4(b[1], sb + bLd + 16 * ROWB + ks * 32);
            #pragma unroll
            for (int f = 0; f < 4; f++) {
                mma16816(acc[f][0], a[f], &b[0][0]);
                mma16816(acc[f][1], a[f], &b[0][2]);
                mma16816(acc[f][2], a[f], &b[1][0]);
                mma16816(acc[f][3], a[f], &b[1][2]);
            }
        }
    }

    float* C = (blockIdx.z == 0) ? C0 : (blockIdx.z == 1) ? C1
             : (blockIdx.z == 2) ? C2 : C3;
    const int gid = lane >> 2;
    const int tig = lane & 3;
    #pragma unroll
    for (int f = 0; f < 4; f++) {
        int rbase = m0 + wm * 64 + f * 16 + gid;
        #pragma unroll
        for (int j = 0; j < 4; j++) {
            int col = n0 + wn * 32 + j * 8 + tig * 2;
            float2 v0 = { acc[f][j][0], acc[f][j][1] };
            float2 v1 = { acc[f][j][2], acc[f][j][3] };
            if (RELU) {
                v0.x = fmaxf(v0.x, 0.f); v0.y = fmaxf(v0.y, 0.f);
                v1.x = fmaxf(v1.x, 0.f); v1.y = fmaxf(v1.y, 0.f);
            }
            *reinterpret_cast<float2*>(C + (size_t)rbase * DIM + col) = v0;
            *reinterpret_cast<float2*>(C + (size_t)(rbase + 8) * DIM + col) = v1;
        }
    }
}

// ---------------------------------------------------------------------------
// GCN branch — CSR build + gather (no fp32 atomics)
// ---------------------------------------------------------------------------
__global__ void deg_zero_kernel()
{
    int i = blockIdx.x * blockDim.x + threadIdx.x;
    if (i < N_NODES) g_degi[i] = 0;
}
__global__ void deg_count_kernel()
{
    int e = blockIdx.x * blockDim.x + threadIdx.x;
    if (e < N_EDGES) atomicAdd(&g_degi[g_dst[e]], 1);
}
// single block, 1024 threads: exclusive scan of g_degi -> g_rowoff; dis; cursor
__global__ __launch_bounds__(1024) void csr_scan_kernel()
{
    __shared__ int part[1024];
    int t = threadIdx.x;
    int v0 = g_degi[4 * t + 0], v1 = g_degi[4 * t + 1];
    int v2 = g_degi[4 * t + 2], v3 = g_degi[4 * t + 3];
    int s1 = v0 + v1, s2 = s1 + v2, s3 = s2 + v3;
    part[t] = s3;
    __syncthreads();
    #pragma unroll
    for (int off = 1; off < 1024; off <<= 1) {
        int x = (t >= off) ? part[t - off] : 0;
        __syncthreads();
        part[t] += x;
        __syncthreads();
    }
    int base = t ? part[t - 1] : 0;
    g_rowoff[4 * t + 0] = base;
    g_rowoff[4 * t + 1] = base + v0;
    g_rowoff[4 * t + 2] = base + s1;
    g_rowoff[4 * t + 3] = base + s2;
    if (t == 1023) g_rowoff[4096] = base + s3;
    #pragma unroll
    for (int i = 0; i < 4; i++) {
        int n = 4 * t + i;
        int d = g_degi[n];
        g_dis[n] = rsqrtf((float)(d + 1));
        g_cursor[n] = 0;
    }
}
__global__ void csr_place_kernel()
{
    int e = blockIdx.x * blockDim.x + threadIdx.x;
    if (e >= N_EDGES) return;
    int dst = g_dst[e];
    int pos = g_rowoff[dst] + atomicAdd(&g_cursor[dst], 1);
    g_csr[pos] = g_src[e];
}
// one CTA per dst row: Hl[dst] = dis[dst]^2 * XW[dst] + sum_e dis[src]dis[dst] XW[src]
__global__ __launch_bounds__(256) void gather_kernel(float* __restrict__ out)
{
    int dst = blockIdx.x;
    int col = threadIdx.x;
    float disD = g_dis[dst];
    float acc = g_A[(size_t)dst * DIM + col] * disD * disD;
    int beg = g_rowoff[dst], end = g_rowoff[dst + 1];
    int j = beg;
    for (; j + 1 < end; j += 2) {
        int s0 = g_csr[j], s1 = g_csr[j + 1];
        float w0 = g_dis[s0] * disD, w1 = g_dis[s1] * disD;
        float x0 = g_A[(size_t)s0 * DIM + col];
        float x1 = g_A[(size_t)s1 * DIM + col];
        acc += x0 * w0 + x1 * w1;
    }
    if (j < end) {
        int s0 = g_csr[j];
        acc += g_A[(size_t)s0 * DIM + col] * (g_dis[s0] * disD);
    }
    out[(size_t)dst * DIM + col] = acc;
}
__global__ void combine_kernel(float* __restrict__ out,
                               const float* __restrict__ b,
                               const float* __restrict__ aLp,
                               const float* __restrict__ aHp)
{
    int id = blockIdx.x * blockDim.x + threadIdx.x;
    if (id >= N_NODES * DIM / 4) return;
    float aL = aLp[0], aH = aHp[0];
    int c4 = (id & (DIM / 4 - 1)) << 2;
    float4 hl = reinterpret_cast<const float4*>(out)[id];
    float4 h0 = reinterpret_cast<const float4*>(g_P0)[id];
    float4 h1 = reinterpret_cast<const float4*>(g_P1)[id];
    float4 h2 = reinterpret_cast<const float4*>(g_P2)[id];
    float4 h3 = reinterpret_cast<const float4*>(g_P3)[id];
    float4 bb = *reinterpret_cast<const float4*>(b + c4);
    float4 r;
    r.x = aL * (hl.x + bb.x) + aH * ((h0.x + h1.x) + (h2.x + h3.x));
    r.y = aL * (hl.y + bb.y) + aH * ((h0.y + h1.y) + (h2.y + h3.y));
    r.z = aL * (hl.z + bb.z) + aH * ((h0.z + h1.z) + (h2.z + h3.z));
    r.w = aL * (hl.w + bb.w) + aH * ((h0.w + h1.w) + (h2.w + h3.w));
    reinterpret_cast<float4*>(out)[id] = r;
}

// ---------------------------------------------------------------------------
extern "C" void kernel_launch(void* const* d_in, const int* in_sizes, int n_in,
                              void* d_out, int out_size)
{
    const float* x      = (const float*)d_in[0];
    const void*  ei_raw = d_in[1];
    const float* lap    = (const float*)d_in[2];
    const float* d_inv  = (const float*)d_in[3];
    const float* W_high = (const float*)d_in[4];
    const float* W_conv = (const float*)d_in[5];
    const float* b_conv = (const float*)d_in[6];
    const float* aL     = (const float*)d_in[7];
    const float* aH     = (const float*)d_in[8];
    float*       out    = (float*)d_out;

    float *pA, *pP0, *pP1, *pP2, *pP3;
    cudaGetSymbolAddress((void**)&pA,  g_A);
    cudaGetSymbolAddress((void**)&pP0, g_P0);
    cudaGetSymbolAddress((void**)&pP1, g_P1);
    cudaGetSymbolAddress((void**)&pP2, g_P2);
    cudaGetSymbolAddress((void**)&pP3, g_P3);
    __nv_bfloat16 *pDh, *pDl, *pLh, *pLl, *pBh, *pBl, *pXh, *pXl, *pWh, *pWl;
    cudaGetSymbolAddress((void**)&pDh, g_dinv_hi);
    cudaGetSymbolAddress((void**)&pDl, g_dinv_lo);
    cudaGetSymbolAddress((void**)&pLh, g_lap_hi);
    cudaGetSymbolAddress((void**)&pLl, g_lap_lo);
    cudaGetSymbolAddress((void**)&pBh, g_Bhi);
    cudaGetSymbolAddress((void**)&pBl, g_Blo);
    cudaGetSymbolAddress((void**)&pXh, g_xhi);
    cudaGetSymbolAddress((void**)&pXl, g_xlo);
    cudaGetSymbolAddress((void**)&pWh, g_Wth);
    cudaGetSymbolAddress((void**)&pWl, g_Wtl);

    cudaFuncSetAttribute(gemm_mma_kernel<false>, cudaFuncAttributeMaxDynamicSharedMemorySize, GEMM_SMEM);
    cudaFuncSetAttribute(gemm_mma_kernel<true >, cudaFuncAttributeMaxDynamicSharedMemorySize, GEMM_SMEM);

    // Edge normalization + CSR build
    detect_dtype_kernel <<<1, 32>>>((const unsigned int*)ei_raw);
    convert_edges_kernel<<<N_EDGES / 256, 256>>>(ei_raw);
    deg_zero_kernel     <<<N_NODES / 256, 256>>>();
    deg_count_kernel    <<<N_EDGES / 256, 256>>>();
    csr_scan_kernel     <<<1, 1024>>>();
    csr_place_kernel    <<<N_EDGES / 256, 256>>>();

    // Splits of inputs
    int nbig8 = N_NODES * N_NODES / 8;
    split_kernel<<<nbig8 / 256, 256>>>((const float4*)d_inv, (uint4*)pDh, (uint4*)pDl, nbig8);
    split_kernel<<<nbig8 / 256, 256>>>((const float4*)lap,   (uint4*)pLh, (uint4*)pLl, nbig8);
    int nx8 = N_NODES * DIM / 8;
    split_kernel<<<nx8 / 256, 256>>>((const float4*)x, (uint4*)pXh, (uint4*)pXl, nx8);

    dim3 gBig(DIM / 128, N_NODES / 128, 4);  // (2, 32, 4) = 256 CTAs
    dim3 gSm (DIM / 128, N_NODES / 128, 1);  // (2, 32, 1)
    dim3 gTr(N_NODES / 32, DIM / 32);
    dim3 bTr(32, 8);
    dim3 gWt(DIM / 32, DIM / 32);
    const int NIT_BIG = (3 * N_NODES / 64) / 4;   // 48 per z
    const int NIT_SM  = 3 * DIM / 64;             // 12
    const int SEG_BIG = 6;                        // 64 iters / segment
    const int SEG_SM  = 2;                        // 4 iters / segment

    // R = relu(x @ W_high)
    wtranspose_split_kernel<<<gWt, bTr>>>(W_high, pWh, pWl);
    gemm_mma_kernel<true><<<gSm, 256, GEMM_SMEM>>>(pXh, pXl, pWh, pWl,
        pA, pA, pA, pA, DIM, DIM, NIT_SM, SEG_SM);
    transpose_split_kernel<1><<<gTr, bTr>>>(pA, nullptr, nullptr, nullptr, pBh, pBl);
    // T1 = d_inv @ R
    gemm_mma_kernel<false><<<gBig, 256, GEMM_SMEM>>>(pDh, pDl, pBh, pBl,
        pP0, pP1, pP2, pP3, N_NODES, N_NODES, NIT_BIG, SEG_BIG);
    // XW_conv = x @ W_conv (into g_A)
    wtranspose_split_kernel<<<gWt, bTr>>>(W_conv, pWh, pWl);
    gemm_mma_kernel<false><<<gSm, 256, GEMM_SMEM>>>(pXh, pXl, pWh, pWl,
        pA, pA, pA, pA, DIM, DIM, NIT_SM, SEG_SM);
    // T2 = lap @ T1
    transpose_split_kernel<4><<<gTr, bTr>>>(pP0, pP1, pP2, pP3, pBh, pBl);
    gemm_mma_kernel<false><<<gBig, 256, GEMM_SMEM>>>(pLh, pLl, pBh, pBl,
        pP0, pP1, pP2, pP3, N_NODES, N_NODES, NIT_BIG, SEG_BIG);
    // Hh = d_inv @ T2 (parts stay in P0..P3)
    transpose_split_kernel<4><<<gTr, bTr>>>(pP0, pP1, pP2, pP3, pBh, pBl);
    gemm_mma_kernel<false><<<gBig, 256, GEMM_SMEM>>>(pDh, pDl, pBh, pBl,
        pP0, pP1, pP2, pP3, N_NODES, N_NODES, NIT_BIG, SEG_BIG);

    // GCN gather: Hl -> out, then combine
    gather_kernel <<<N_NODES, 256>>>(out);
    int nvec = N_NODES * DIM / 4;
    combine_kernel<<<(nvec + 255) / 256, 256>>>(out, b_conv, aL, aH);
}

// round 9
// speedup vs baseline: 1.2636x; 1.0226x over previous
#include <cuda_runtime.h>
#include <cuda_bf16.h>
#include <cuda_fp16.h>
#include <cstdint>

// FBGCN layer:
//   Hh = d_inv @ (lap @ (d_inv @ relu(x @ W_high)))  -- mma.sync bf16-split GEMMs
//   Hl = GCNConv(x, edge_index, W_conv, b_conv)      -- CSR gather (fp16 features)
//   out = aL*Hl + aH*Hh

static constexpr int N_NODES = 4096;
static constexpr int DIM     = 256;
static constexpr int N_EDGES = 131072;

// fp32 scratch
__device__ __align__(16) float g_A[N_NODES * DIM];    // R
__device__ __align__(16) float g_P0[N_NODES * DIM];   // split-K partials
__device__ __align__(16) float g_P1[N_NODES * DIM];
__device__ __align__(16) float g_P2[N_NODES * DIM];
__device__ __align__(16) float g_P3[N_NODES * DIM];
__device__ __align__(16) __half g_XWh[N_NODES * DIM]; // XW_conv in fp16
__device__ float g_dis[N_NODES];
__device__ int   g_src[N_EDGES];
__device__ int   g_dst[N_EDGES];
__device__ int   g_is64;
// CSR
__device__ int   g_degi[N_NODES];
__device__ int   g_rowoff[N_NODES + 1];
__device__ int   g_cursor[N_NODES];
__device__ int   g_csr[N_EDGES];

// bf16 split buffers
__device__ __align__(128) __nv_bfloat16 g_dinv_hi[N_NODES * N_NODES];
__device__ __align__(128) __nv_bfloat16 g_dinv_lo[N_NODES * N_NODES];
__device__ __align__(128) __nv_bfloat16 g_lap_hi [N_NODES * N_NODES];
__device__ __align__(128) __nv_bfloat16 g_lap_lo [N_NODES * N_NODES];
__device__ __align__(128) __nv_bfloat16 g_Bhi[DIM * N_NODES];   // [256 x 4096] act^T
__device__ __align__(128) __nv_bfloat16 g_Blo[DIM * N_NODES];
__device__ __align__(128) __nv_bfloat16 g_xhi[N_NODES * DIM];   // x splits (K-major rows)
__device__ __align__(128) __nv_bfloat16 g_xlo[N_NODES * DIM];
__device__ __align__(128) __nv_bfloat16 g_Wth[DIM * DIM];       // W^T splits
__device__ __align__(128) __nv_bfloat16 g_Wtl[DIM * DIM];

// ---------------------------------------------------------------------------
// PTX helpers (baseline ISA only: cp.async, ldmatrix, mma.sync)
// ---------------------------------------------------------------------------
__device__ __forceinline__ uint32_t smem_u32(const void* p) {
    uint32_t a;
    asm("{ .reg .u64 t; cvta.to.shared.u64 t, %1; cvt.u32.u64 %0, t; }" : "=r"(a) : "l"(p));
    return a;
}
__device__ __forceinline__ void cp_async16(uint32_t dst, const void* src) {
    asm volatile("cp.async.cg.shared.global [%0], [%1], 16;" :: "r"(dst), "l"(src) : "memory");
}
__device__ __forceinline__ void cp_commit() { asm volatile("cp.async.commit_group;" ::: "memory"); }
template <int N>
__device__ __forceinline__ void cp_wait() { asm volatile("cp.async.wait_group %0;" :: "n"(N) : "memory"); }

__device__ __forceinline__ void ldsm_x4(uint32_t* r, uint32_t addr) {
    asm volatile("ldmatrix.sync.aligned.m8n8.x4.shared.b16 {%0,%1,%2,%3}, [%4];"
        : "=r"(r[0]), "=r"(r[1]), "=r"(r[2]), "=r"(r[3]) : "r"(addr));
}
__device__ __forceinline__ void mma16816(float* c, const uint32_t* a, const uint32_t* b) {
    asm volatile("mma.sync.aligned.m16n8k16.row.col.f32.bf16.bf16.f32 "
        "{%0,%1,%2,%3}, {%4,%5,%6,%7}, {%8,%9}, {%0,%1,%2,%3};"
        : "+f"(c[0]), "+f"(c[1]), "+f"(c[2]), "+f"(c[3])
        : "r"(a[0]), "r"(a[1]), "r"(a[2]), "r"(a[3]), "r"(b[0]), "r"(b[1]));
}

// ---------------------------------------------------------------------------
// detect dtype + zero degree counters (block 0 detects, blocks 1..16 zero)
// ---------------------------------------------------------------------------
__global__ void detect_init_kernel(const unsigned int* __restrict__ raw)
{
    int b = blockIdx.x;
    if (b == 0) {
        if (threadIdx.x == 0) {
            int is64 = 1;
            #pragma unroll 1
            for (int i = 0; i < 128; i++)
                if (raw[2 * i + 1] != 0u) { is64 = 0; break; }
            g_is64 = is64;
        }
    } else {
        g_degi[(b - 1) * 256 + threadIdx.x] = 0;
    }
}
// convert + count degrees in one pass
__global__ void convert_edges_kernel(const void* __restrict__ rawp)
{
    int e = blockIdx.x * blockDim.x + threadIdx.x;
    if (e >= N_EDGES) return;
    int s, d;
    if (g_is64) {
        const long long* ei = (const long long*)rawp;
        s = (int)ei[e];
        d = (int)ei[N_EDGES + e];
    } else {
        const int* ei = (const int*)rawp;
        s = ei[e];
        d = ei[N_EDGES + e];
    }
    g_src[e] = s;
    g_dst[e] = d;
    atomicAdd(&g_degi[d], 1);
}

// ---------------------------------------------------------------------------
// fp32 -> (hi, lo) bf16 split, 8 elements per thread, uint4 stores
// ---------------------------------------------------------------------------
__global__ void split_kernel(const float4* __restrict__ src,
                             uint4* __restrict__ hi, uint4* __restrict__ lo, int n8)
{
    int id = blockIdx.x * blockDim.x + threadIdx.x;
    if (id >= n8) return;
    float4 a = src[2 * id], b = src[2 * id + 1];
    float f[8] = { a.x, a.y, a.z, a.w, b.x, b.y, b.z, b.w };
    uint32_t H[4], L[4];
    #pragma unroll
    for (int i = 0; i < 4; i++) {
        __nv_bfloat16 h0 = __float2bfloat16(f[2 * i + 0]);
        __nv_bfloat16 h1 = __float2bfloat16(f[2 * i + 1]);
        __nv_bfloat16 l0 = __float2bfloat16(f[2 * i + 0] - __bfloat162float(h0));
        __nv_bfloat16 l1 = __float2bfloat16(f[2 * i + 1] - __bfloat162float(h1));
        __nv_bfloat162 hh(h0, h1), ll(l0, l1);
        H[i] = *(uint32_t*)&hh;
        L[i] = *(uint32_t*)&ll;
    }
    hi[id] = make_uint4(H[0], H[1], H[2], H[3]);
    lo[id] = make_uint4(L[0], L[1], L[2], L[3]);
}

// ---------------------------------------------------------------------------
// activations: fp32 [4096 x 256] (sum of NSUM buffers) -> bf16 splits [256 x 4096]
// ---------------------------------------------------------------------------
template <int NSUM>
__global__ void transpose_split_kernel(const float* __restrict__ s0,
                                       const float* __restrict__ s1,
                                       const float* __restrict__ s2,
                                       const float* __restrict__ s3,
                                       __nv_bfloat16* __restrict__ hi,
                                       __nv_bfloat16* __restrict__ lo)
{
    __shared__ float tile[32][33];
    int k0 = blockIdx.x * 32;
    int n0 = blockIdx.y * 32;
    int tx = threadIdx.x, ty = threadIdx.y;    // 32 x 8
    #pragma unroll
    for (int j = 0; j < 4; j++) {
        size_t o = (size_t)(k0 + ty + j * 8) * DIM + n0 + tx;
        float v = s0[o];
        if (NSUM > 1) v += s1[o];
        if (NSUM > 2) v += s2[o];
        if (NSUM > 3) v += s3[o];
        tile[ty + j * 8][tx] = v;
    }
    __syncthreads();
    #pragma unroll
    for (int j = 0; j < 4; j++) {
        int n = ty + j * 8;
        float v = tile[tx][n];
        __nv_bfloat16 h = __float2bfloat16(v);
        __nv_bfloat16 l = __float2bfloat16(v - __bfloat162float(h));
        size_t o = (size_t)(n0 + n) * N_NODES + k0 + tx;
        hi[o] = h; lo[o] = l;
    }
}

// W [256 x 256] fp32 row-major -> W^T bf16 splits [256 x 256]
__global__ void wtranspose_split_kernel(const float* __restrict__ W,
                                        __nv_bfloat16* __restrict__ hi,
                                        __nv_bfloat16* __restrict__ lo)
{
    __shared__ float tile[32][33];
    int k0 = blockIdx.x * 32;
    int n0 = blockIdx.y * 32;
    int tx = threadIdx.x, ty = threadIdx.y;    // 32 x 8
    #pragma unroll
    for (int j = 0; j < 4; j++)
        tile[ty + j * 8][tx] = W[(size_t)(k0 + ty + j * 8) * DIM + n0 + tx];
    __syncthreads();
    #pragma unroll
    for (int j = 0; j < 4; j++) {
        int n = ty + j * 8;
        float v = tile[tx][n];
        __nv_bfloat16 h = __float2bfloat16(v);
        __nv_bfloat16 l = __float2bfloat16(v - __bfloat162float(h));
        size_t o = (size_t)(n0 + n) * DIM + k0 + tx;
        hi[o] = h; lo[o] = l;
    }
}

// ---------------------------------------------------------------------------
// mma.sync GEMM (R6 config): C[4096 x 256] f32, 3-term bf16 split, split-K.
// CTA tile 128(M) x 128(N), BK=64, 256 threads / 8 warps (2m x 4n), warp 64x32.
// ROWB=144: cp.async writes and ldmatrix reads both bank-conflict-free.
// 3-stage cp.async pipeline, 2 CTAs/SM. blockIdx.z selects K chunk -> partial.
// HOUT: write half2 output (for XW_conv -> gather) instead of fp32.
// ---------------------------------------------------------------------------
static constexpr int STAGES   = 3;
static constexpr int ROWB     = 144;                  // 128B data + 16B pad
static constexpr int A_BYTES  = 128 * ROWB;           // 18432
static constexpr int STAGE_B  = 2 * A_BYTES;          // 36864
static constexpr int GEMM_SMEM = STAGES * STAGE_B;    // 110592

template <bool RELU, bool HOUT>
__global__ __launch_bounds__(256, 2) void gemm_mma_kernel(
    const __nv_bfloat16* __restrict__ Ahi, const __nv_bfloat16* __restrict__ Alo,
    const __nv_bfloat16* __restrict__ Bhi, const __nv_bfloat16* __restrict__ Blo,
    float* __restrict__ C0, float* __restrict__ C1,
    float* __restrict__ C2, float* __restrict__ C3,
    __half* __restrict__ Ch,
    int strideA, int strideB, int nit, int segShift)
{
    extern __shared__ char smem[];
    const uint32_t sbase = smem_u32(smem);
    const int t    = threadIdx.x;
    const int lane = t & 31;
    const int wid  = t >> 5;
    const int wm   = wid >> 2;       // 0..1 -> M offset wm*64
    const int wn   = wid & 3;        // 0..3 -> N offset wn*32
    const int m0   = blockIdx.y * 128;
    const int n0   = blockIdx.x * 128;
    const int cBeg = blockIdx.z * nit;
    const int segMask = (1 << segShift) - 1;

    const __nv_bfloat16* Aseg[3] = { Ahi, Ahi, Alo };
    const __nv_bfloat16* Bseg[3] = { Bhi, Blo, Bhi };

    // cp.async task mapping: 8 tasks/thread (4 A rows + 4 B rows), ch = t&7
    const int rowBase = t >> 3;          // 0..31
    const int ch      = t & 7;
    uint32_t aOffG[4], bOffG[4], sOffA[4];
    #pragma unroll
    for (int i = 0; i < 4; i++) {
        int row = rowBase + 32 * i;
        aOffG[i] = (uint32_t)((m0 + row) * strideA + ch * 8);
        bOffG[i] = (uint32_t)((n0 + row) * strideB + ch * 8);
        sOffA[i] = (uint32_t)(row * ROWB + ch * 16);
    }

    // ldmatrix lane bases (byte offsets within stage)
    const uint32_t aLd = (uint32_t)(wm * 64 + (lane & 15)) * ROWB + (lane >> 4) * 16;
    const uint32_t bLd = A_BYTES +
        (uint32_t)(wn * 32 + ((lane >> 4) & 1) * 8 + (lane & 7)) * ROWB + ((lane >> 3) & 1) * 16;

    float acc[4][4][4];
    #pragma unroll
    for (int f = 0; f < 4; f++)
        #pragma unroll
        for (int j = 0; j < 4; j++)
            #pragma unroll
            for (int e = 0; e < 4; e++) acc[f][j][e] = 0.f;

    auto load_stage = [&](int ci, int s) {
        if (ci < nit) {
            int c   = cBeg + ci;
            int seg = c >> segShift;
            int k0  = (c & segMask) << 6;
            const __nv_bfloat16* ap = Aseg[seg] + k0;
            const __nv_bfloat16* bp = Bseg[seg] + k0;
            uint32_t sb = sbase + s * STAGE_B;
            #pragma unroll
            for (int i = 0; i < 4; i++) cp_async16(sb + sOffA[i], ap + aOffG[i]);
            #pragma unroll
            for (int i = 0; i < 4; i++) cp_async16(sb + A_BYTES + sOffA[i], bp + bOffG[i]);
        }
        cp_commit();
    };

    load_stage(0, 0);
    load_stage(1, 1);

    for (int ci = 0; ci < nit; ci++) {
        cp_wait<STAGES - 2>();
        __syncthreads();
        load_stage(ci + STAGES - 1, (ci + STAGES - 1) % STAGES);

        uint32_t sb = sbase + (ci % STAGES) * STAGE_B;
        #pragma unroll
        for (int ks = 0; ks < 4; ks++) {
            uint32_t a[4][4], b[2][4];
            #pragma unroll
            for (int f = 0; f < 4; f++)
                ldsm_x4(a[f], sb + aLd + f * 16 * ROWB + ks * 32);
            ldsm_x4(b[0], sb + bLd + ks * 32);
            ldsm_x4(b[1], sb + bLd + 16 * ROWB + ks * 32);
            #pragma unroll
            for (int f = 0; f < 4; f++) {
                mma16816(acc[f][0], a[f], &b[0][0]);
                mma16816(acc[f][1], a[f], &b[0][2]);
                mma16816(acc[f][2], a[f], &b[1][0]);
                mma16816(acc[f][3], a[f], &b[1][2]);
            }
        }
    }

    float* C = (blockIdx.z == 0) ? C0 : (blockIdx.z == 1) ? C1
             : (blockIdx.z == 2) ? C2 : C3;
    const int gid = lane >> 2;
    const int tig = lane & 3;
    #pragma unroll
    for (int f = 0; f < 4; f++) {
        int rbase = m0 + wm * 64 + f * 16 + gid;
        #pragma unroll
        for (int j = 0; j < 4; j++) {
            int col = n0 + wn * 32 + j * 8 + tig * 2;
            float2 v0 = { acc[f][j][0], acc[f][j][1] };
            float2 v1 = { acc[f][j][2], acc[f][j][3] };
            if (RELU) {
                v0.x = fmaxf(v0.x, 0.f); v0.y = fmaxf(v0.y, 0.f);
                v1.x = fmaxf(v1.x, 0.f); v1.y = fmaxf(v1.y, 0.f);
            }
            if (HOUT) {
                __half2* Hp = (__half2*)Ch;
                Hp[((size_t)rbase * DIM + col) >> 1]       = __floats2half2_rn(v0.x, v0.y);
                Hp[((size_t)(rbase + 8) * DIM + col) >> 1] = __floats2half2_rn(v1.x, v1.y);
            } else {
                *reinterpret_cast<float2*>(C + (size_t)rbase * DIM + col) = v0;
                *reinterpret_cast<float2*>(C + (size_t)(rbase + 8) * DIM + col) = v1;
            }
        }
    }
}

// ---------------------------------------------------------------------------
// CSR build + gather
// ---------------------------------------------------------------------------
// single block, 1024 threads: exclusive scan of g_degi -> g_rowoff; dis; cursor
__global__ __launch_bounds__(1024) void csr_scan_kernel()
{
    __shared__ int part[1024];
    int t = threadIdx.x;
    int v0 = g_degi[4 * t + 0], v1 = g_degi[4 * t + 1];
    int v2 = g_degi[4 * t + 2], v3 = g_degi[4 * t + 3];
    int s1 = v0 + v1, s2 = s1 + v2, s3 = s2 + v3;
    part[t] = s3;
    __syncthreads();
    #pragma unroll
    for (int off = 1; off < 1024; off <<= 1) {
        int x = (t >= off) ? part[t - off] : 0;
        __syncthreads();
        part[t] += x;
        __syncthreads();
    }
    int base = t ? part[t - 1] : 0;
    g_rowoff[4 * t + 0] = base;
    g_rowoff[4 * t + 1] = base + v0;
    g_rowoff[4 * t + 2] = base + s1;
    g_rowoff[4 * t + 3] = base + s2;
    if (t == 1023) g_rowoff[4096] = base + s3;
    #pragma unroll
    for (int i = 0; i < 4; i++) {
        int n = 4 * t + i;
        int d = g_degi[n];
        g_dis[n] = rsqrtf((float)(d + 1));
        g_cursor[n] = 0;
    }
}
__global__ void csr_place_kernel()
{
    int e = blockIdx.x * blockDim.x + threadIdx.x;
    if (e >= N_EDGES) return;
    int dst = g_dst[e];
    int pos = g_rowoff[dst] + atomicAdd(&g_cursor[dst], 1);
    g_csr[pos] = g_src[e];
}
// one CTA (128 threads, 2 cols each) per dst row, fp16 features:
// Hl[dst] = dis[dst]^2 * XW[dst] + sum_e dis[src]dis[dst] XW[src]
__global__ __launch_bounds__(128) void gather_kernel(float* __restrict__ out)
{
    int dst = blockIdx.x;
    int t   = threadIdx.x;                 // col pair index 0..127
    const __half2* XW = (const __half2*)g_XWh;
    float disD = g_dis[dst];
    float2 sv = __half22float2(XW[(size_t)dst * 128 + t]);
    float accx = sv.x * disD * disD;
    float accy = sv.y * disD * disD;
    int beg = g_rowoff[dst], end = g_rowoff[dst + 1];
    int j = beg;
    for (; j + 1 < end; j += 2) {
        int s0 = g_csr[j], s1 = g_csr[j + 1];
        float w0 = g_dis[s0] * disD, w1 = g_dis[s1] * disD;
        float2 v0 = __half22float2(XW[(size_t)s0 * 128 + t]);
        float2 v1 = __half22float2(XW[(size_t)s1 * 128 + t]);
        accx += v0.x * w0 + v1.x * w1;
        accy += v0.y * w0 + v1.y * w1;
    }
    if (j < end) {
        int s0 = g_csr[j];
        float w0 = g_dis[s0] * disD;
        float2 v0 = __half22float2(XW[(size_t)s0 * 128 + t]);
        accx += v0.x * w0;
        accy += v0.y * w0;
    }
    *reinterpret_cast<float2*>(out + (size_t)dst * DIM + 2 * t) = make_float2(accx, accy);
}
__global__ void combine_kernel(float* __restrict__ out,
                               const float* __restrict__ b,
                               const float* __restrict__ aLp,
                               const float* __restrict__ aHp)
{
    int id = blockIdx.x * blockDim.x + threadIdx.x;
    if (id >= N_NODES * DIM / 4) return;
    float aL = aLp[0], aH = aHp[0];
    int c4 = (id & (DIM / 4 - 1)) << 2;
    float4 hl = reinterpret_cast<const float4*>(out)[id];
    float4 h0 = reinterpret_cast<const float4*>(g_P0)[id];
    float4 h1 = reinterpret_cast<const float4*>(g_P1)[id];
    float4 h2 = reinterpret_cast<const float4*>(g_P2)[id];
    float4 h3 = reinterpret_cast<const float4*>(g_P3)[id];
    float4 bb = *reinterpret_cast<const float4*>(b + c4);
    float4 r;
    r.x = aL * (hl.x + bb.x) + aH * ((h0.x + h1.x) + (h2.x + h3.x));
    r.y = aL * (hl.y + bb.y) + aH * ((h0.y + h1.y) + (h2.y + h3.y));
    r.z = aL * (hl.z + bb.z) + aH * ((h0.z + h1.z) + (h2.z + h3.z));
    r.w = aL * (hl.w + bb.w) + aH * ((h0.w + h1.w) + (h2.w + h3.w));
    reinterpret_cast<float4*>(out)[id] = r;
}

// ---------------------------------------------------------------------------
extern "C" void kernel_launch(void* const* d_in, const int* in_sizes, int n_in,
                              void* d_out, int out_size)
{
    const float* x      = (const float*)d_in[0];
    const void*  ei_raw = d_in[1];
    const float* lap    = (const float*)d_in[2];
    const float* d_inv  = (const float*)d_in[3];
    const float* W_high = (const float*)d_in[4];
    const float* W_conv = (const float*)d_in[5];
    const float* b_conv = (const float*)d_in[6];
    const float* aL     = (const float*)d_in[7];
    const float* aH     = (const float*)d_in[8];
    float*       out    = (float*)d_out;

    float *pA, *pP0, *pP1, *pP2, *pP3;
    cudaGetSymbolAddress((void**)&pA,  g_A);
    cudaGetSymbolAddress((void**)&pP0, g_P0);
    cudaGetSymbolAddress((void**)&pP1, g_P1);
    cudaGetSymbolAddress((void**)&pP2, g_P2);
    cudaGetSymbolAddress((void**)&pP3, g_P3);
    __half* pXWh;
    cudaGetSymbolAddress((void**)&pXWh, g_XWh);
    __nv_bfloat16 *pDh, *pDl, *pLh, *pLl, *pBh, *pBl, *pXh, *pXl, *pWh, *pWl;
    cudaGetSymbolAddress((void**)&pDh, g_dinv_hi);
    cudaGetSymbolAddress((void**)&pDl, g_dinv_lo);
    cudaGetSymbolAddress((void**)&pLh, g_lap_hi);
    cudaGetSymbolAddress((void**)&pLl, g_lap_lo);
    cudaGetSymbolAddress((void**)&pBh, g_Bhi);
    cudaGetSymbolAddress((void**)&pBl, g_Blo);
    cudaGetSymbolAddress((void**)&pXh, g_xhi);
    cudaGetSymbolAddress((void**)&pXl, g_xlo);
    cudaGetSymbolAddress((void**)&pWh, g_Wth);
    cudaGetSymbolAddress((void**)&pWl, g_Wtl);

    cudaFuncSetAttribute(gemm_mma_kernel<false, false>, cudaFuncAttributeMaxDynamicSharedMemorySize, GEMM_SMEM);
    cudaFuncSetAttribute(gemm_mma_kernel<true,  false>, cudaFuncAttributeMaxDynamicSharedMemorySize, GEMM_SMEM);
    cudaFuncSetAttribute(gemm_mma_kernel<false, true >, cudaFuncAttributeMaxDynamicSharedMemorySize, GEMM_SMEM);

    // Edge normalization + CSR build (degree counting fused into convert)
    detect_init_kernel  <<<17, 256>>>((const unsigned int*)ei_raw);
    convert_edges_kernel<<<N_EDGES / 256, 256>>>(ei_raw);
    csr_scan_kernel     <<<1, 1024>>>();
    csr_place_kernel    <<<N_EDGES / 256, 256>>>();

    // Splits of inputs
    int nbig8 = N_NODES * N_NODES / 8;
    split_kernel<<<nbig8 / 256, 256>>>((const float4*)d_inv, (uint4*)pDh, (uint4*)pDl, nbig8);
    split_kernel<<<nbig8 / 256, 256>>>((const float4*)lap,   (uint4*)pLh, (uint4*)pLl, nbig8);
    int nx8 = N_NODES * DIM / 8;
    split_kernel<<<nx8 / 256, 256>>>((const float4*)x, (uint4*)pXh, (uint4*)pXl, nx8);

    dim3 gBig(DIM / 128, N_NODES / 128, 4);  // (2, 32, 4) = 256 CTAs
    dim3 gSm (DIM / 128, N_NODES / 128, 1);  // (2, 32, 1)
    dim3 gTr(N_NODES / 32, DIM / 32);
    dim3 bTr(32, 8);
    dim3 gWt(DIM / 32, DIM / 32);
    const int NIT_BIG = (3 * N_NODES / 64) / 4;   // 48 per z
    const int NIT_SM  = 3 * DIM / 64;             // 12
    const int SEG_BIG = 6;                        // 64 iters / segment
    const int SEG_SM  = 2;                        // 4 iters / segment

    // R = relu(x @ W_high)
    wtranspose_split_kernel<<<gWt, bTr>>>(W_high, pWh, pWl);
    gemm_mma_kernel<true, false><<<gSm, 256, GEMM_SMEM>>>(pXh, pXl, pWh, pWl,
        pA, pA, pA, pA, nullptr, DIM, DIM, NIT_SM, SEG_SM);
    transpose_split_kernel<1><<<gTr, bTr>>>(pA, nullptr, nullptr, nullptr, pBh, pBl);
    // T1 = d_inv @ R
    gemm_mma_kernel<false, false><<<gBig, 256, GEMM_SMEM>>>(pDh, pDl, pBh, pBl,
        pP0, pP1, pP2, pP3, nullptr, N_NODES, N_NODES, NIT_BIG, SEG_BIG);
    // XW_conv = x @ W_conv (fp16, for the gather)
    wtranspose_split_kernel<<<gWt, bTr>>>(W_conv, pWh, pWl);
    gemm_mma_kernel<false, true><<<gSm, 256, GEMM_SMEM>>>(pXh, pXl, pWh, pWl,
        pA, pA, pA, pA, pXWh, DIM, DIM, NIT_SM, SEG_SM);
    // T2 = lap @ T1
    transpose_split_kernel<4><<<gTr, bTr>>>(pP0, pP1, pP2, pP3, pBh, pBl);
    gemm_mma_kernel<false, false><<<gBig, 256, GEMM_SMEM>>>(pLh, pLl, pBh, pBl,
        pP0, pP1, pP2, pP3, nullptr, N_NODES, N_NODES, NIT_BIG, SEG_BIG);
    // Hh = d_inv @ T2 (parts stay in P0..P3)
    transpose_split_kernel<4><<<gTr, bTr>>>(pP0, pP1, pP2, pP3, pBh, pBl);
    gemm_mma_kernel<false, false><<<gBig, 256, GEMM_SMEM>>>(pDh, pDl, pBh, pBl,
        pP0, pP1, pP2, pP3, nullptr, N_NODES, N_NODES, NIT_BIG, SEG_BIG);

    // GCN gather: Hl -> out, then combine
    gather_kernel <<<N_NODES, 128>>>(out);
    int nvec = N_NODES * DIM / 4;
    combine_kernel<<<(nvec + 255) / 256, 256>>>(out, b_conv, aL, aH);
}

// round 10
// speedup vs baseline: 1.2919x; 1.0224x over previous
#include <cuda_runtime.h>
#include <cuda_bf16.h>
#include <cuda_fp16.h>
#include <cstdint>

// FBGCN layer:
//   Hh = d_inv @ (lap @ (d_inv @ relu(x @ W_high)))  -- mma.sync bf16-split GEMMs
//   Hl = GCNConv(x, edge_index, W_conv, b_conv)      -- CSR gather (fp16 features)
//   out = aL*Hl + aH*Hh

static constexpr int N_NODES = 4096;
static constexpr int DIM     = 256;
static constexpr int N_EDGES = 131072;

// fp32 scratch
__device__ __align__(16) float g_A[N_NODES * DIM];    // R
__device__ __align__(16) float g_P0[N_NODES * DIM];   // split-K partials
__device__ __align__(16) float g_P1[N_NODES * DIM];
__device__ __align__(16) float g_P2[N_NODES * DIM];
__device__ __align__(16) float g_P3[N_NODES * DIM];
__device__ __align__(16) __half g_XWh[N_NODES * DIM]; // XW_conv in fp16
__device__ float g_dis[N_NODES];
__device__ int   g_src[N_EDGES];
__device__ int   g_dst[N_EDGES];
__device__ int   g_is64;
// CSR
__device__ int   g_degi[N_NODES];
__device__ int   g_rowoff[N_NODES + 1];
__device__ int   g_cursor[N_NODES];
__device__ int   g_csr[N_EDGES];

// bf16 split buffers
__device__ __align__(128) __nv_bfloat16 g_dinv_hi[N_NODES * N_NODES];
__device__ __align__(128) __nv_bfloat16 g_dinv_lo[N_NODES * N_NODES];
__device__ __align__(128) __nv_bfloat16 g_lap_hi [N_NODES * N_NODES];
__device__ __align__(128) __nv_bfloat16 g_lap_lo [N_NODES * N_NODES];
__device__ __align__(128) __nv_bfloat16 g_Bhi[DIM * N_NODES];   // [256 x 4096] act^T
__device__ __align__(128) __nv_bfloat16 g_Blo[DIM * N_NODES];
__device__ __align__(128) __nv_bfloat16 g_xhi[N_NODES * DIM];   // x splits (K-major rows)
__device__ __align__(128) __nv_bfloat16 g_xlo[N_NODES * DIM];
__device__ __align__(128) __nv_bfloat16 g_Wth[DIM * DIM];       // W^T splits
__device__ __align__(128) __nv_bfloat16 g_Wtl[DIM * DIM];

// ---------------------------------------------------------------------------
// PTX helpers (baseline ISA only: cp.async, ldmatrix, mma.sync)
// ---------------------------------------------------------------------------
__device__ __forceinline__ uint32_t smem_u32(const void* p) {
    uint32_t a;
    asm("{ .reg .u64 t; cvta.to.shared.u64 t, %1; cvt.u32.u64 %0, t; }" : "=r"(a) : "l"(p));
    return a;
}
__device__ __forceinline__ void cp_async16(uint32_t dst, const void* src) {
    asm volatile("cp.async.cg.shared.global [%0], [%1], 16;" :: "r"(dst), "l"(src) : "memory");
}
__device__ __forceinline__ void cp_commit() { asm volatile("cp.async.commit_group;" ::: "memory"); }
template <int N>
__device__ __forceinline__ void cp_wait() { asm volatile("cp.async.wait_group %0;" :: "n"(N) : "memory"); }

__device__ __forceinline__ void ldsm_x4(uint32_t* r, uint32_t addr) {
    asm volatile("ldmatrix.sync.aligned.m8n8.x4.shared.b16 {%0,%1,%2,%3}, [%4];"
        : "=r"(r[0]), "=r"(r[1]), "=r"(r[2]), "=r"(r[3]) : "r"(addr));
}
__device__ __forceinline__ void mma16816(float* c, const uint32_t* a, const uint32_t* b) {
    asm volatile("mma.sync.aligned.m16n8k16.row.col.f32.bf16.bf16.f32 "
        "{%0,%1,%2,%3}, {%4,%5,%6,%7}, {%8,%9}, {%0,%1,%2,%3};"
        : "+f"(c[0]), "+f"(c[1]), "+f"(c[2]), "+f"(c[3])
        : "r"(a[0]), "r"(a[1]), "r"(a[2]), "r"(a[3]), "r"(b[0]), "r"(b[1]));
}

// ---------------------------------------------------------------------------
// detect dtype + zero degree counters (block 0 detects, blocks 1..16 zero)
// ---------------------------------------------------------------------------
__global__ void detect_init_kernel(const unsigned int* __restrict__ raw)
{
    int b = blockIdx.x;
    if (b == 0) {
        if (threadIdx.x == 0) {
            int is64 = 1;
            #pragma unroll 1
            for (int i = 0; i < 128; i++)
                if (raw[2 * i + 1] != 0u) { is64 = 0; break; }
            g_is64 = is64;
        }
    } else {
        g_degi[(b - 1) * 256 + threadIdx.x] = 0;
    }
}
// convert + count degrees in one pass
__global__ void convert_edges_kernel(const void* __restrict__ rawp)
{
    int e = blockIdx.x * blockDim.x + threadIdx.x;
    if (e >= N_EDGES) return;
    int s, d;
    if (g_is64) {
        const long long* ei = (const long long*)rawp;
        s = (int)ei[e];
        d = (int)ei[N_EDGES + e];
    } else {
        const int* ei = (const int*)rawp;
        s = ei[e];
        d = ei[N_EDGES + e];
    }
    g_src[e] = s;
    g_dst[e] = d;
    atomicAdd(&g_degi[d], 1);
}

// ---------------------------------------------------------------------------
// fp32 -> (hi, lo) bf16 split, 8 elements per thread, uint4 stores
// ---------------------------------------------------------------------------
__global__ void split_kernel(const float4* __restrict__ src,
                             uint4* __restrict__ hi, uint4* __restrict__ lo, int n8)
{
    int id = blockIdx.x * blockDim.x + threadIdx.x;
    if (id >= n8) return;
    float4 a = src[2 * id], b = src[2 * id + 1];
    float f[8] = { a.x, a.y, a.z, a.w, b.x, b.y, b.z, b.w };
    uint32_t H[4], L[4];
    #pragma unroll
    for (int i = 0; i < 4; i++) {
        __nv_bfloat16 h0 = __float2bfloat16(f[2 * i + 0]);
        __nv_bfloat16 h1 = __float2bfloat16(f[2 * i + 1]);
        __nv_bfloat16 l0 = __float2bfloat16(f[2 * i + 0] - __bfloat162float(h0));
        __nv_bfloat16 l1 = __float2bfloat16(f[2 * i + 1] - __bfloat162float(h1));
        __nv_bfloat162 hh(h0, h1), ll(l0, l1);
        H[i] = *(uint32_t*)&hh;
        L[i] = *(uint32_t*)&ll;
    }
    hi[id] = make_uint4(H[0], H[1], H[2], H[3]);
    lo[id] = make_uint4(L[0], L[1], L[2], L[3]);
}

// ---------------------------------------------------------------------------
// activations: fp32 [4096 x 256] (sum of NSUM buffers) -> bf16 splits [256 x 4096]
// ---------------------------------------------------------------------------
template <int NSUM>
__global__ void transpose_split_kernel(const float* __restrict__ s0,
                                       const float* __restrict__ s1,
                                       const float* __restrict__ s2,
                                       const float* __restrict__ s3,
                                       __nv_bfloat16* __restrict__ hi,
                                       __nv_bfloat16* __restrict__ lo)
{
    __shared__ float tile[32][33];
    int k0 = blockIdx.x * 32;
    int n0 = blockIdx.y * 32;
    int tx = threadIdx.x, ty = threadIdx.y;    // 32 x 8
    #pragma unroll
    for (int j = 0; j < 4; j++) {
        size_t o = (size_t)(k0 + ty + j * 8) * DIM + n0 + tx;
        float v = s0[o];
        if (NSUM > 1) v += s1[o];
        if (NSUM > 2) v += s2[o];
        if (NSUM > 3) v += s3[o];
        tile[ty + j * 8][tx] = v;
    }
    __syncthreads();
    #pragma unroll
    for (int j = 0; j < 4; j++) {
        int n = ty + j * 8;
        float v = tile[tx][n];
        __nv_bfloat16 h = __float2bfloat16(v);
        __nv_bfloat16 l = __float2bfloat16(v - __bfloat162float(h));
        size_t o = (size_t)(n0 + n) * N_NODES + k0 + tx;
        hi[o] = h; lo[o] = l;
    }
}

// W [256 x 256] fp32 row-major -> W^T bf16 splits [256 x 256]
__global__ void wtranspose_split_kernel(const float* __restrict__ W,
                                        __nv_bfloat16* __restrict__ hi,
                                        __nv_bfloat16* __restrict__ lo)
{
    __shared__ float tile[32][33];
    int k0 = blockIdx.x * 32;
    int n0 = blockIdx.y * 32;
    int tx = threadIdx.x, ty = threadIdx.y;    // 32 x 8
    #pragma unroll
    for (int j = 0; j < 4; j++)
        tile[ty + j * 8][tx] = W[(size_t)(k0 + ty + j * 8) * DIM + n0 + tx];
    __syncthreads();
    #pragma unroll
    for (int j = 0; j < 4; j++) {
        int n = ty + j * 8;
        float v = tile[tx][n];
        __nv_bfloat16 h = __float2bfloat16(v);
        __nv_bfloat16 l = __float2bfloat16(v - __bfloat162float(h));
        size_t o = (size_t)(n0 + n) * DIM + k0 + tx;
        hi[o] = h; lo[o] = l;
    }
}

// ---------------------------------------------------------------------------
// mma.sync GEMM: C[4096 x 256] f32, 3-term bf16 split, split-K via blockIdx.z.
// CTA tile 128(M) x 128(N), BK=64, 128 threads / 4 warps (2m x 2n), warp 64x64.
// ROWB=144: cp.async writes and ldmatrix reads both bank-conflict-free.
// 3-stage cp.async pipeline, 2 CTAs/SM.
// HOUT: write half2 output (for XW_conv -> gather) instead of fp32.
// ---------------------------------------------------------------------------
static constexpr int STAGES   = 3;
static constexpr int ROWB     = 144;                  // 128B data + 16B pad
static constexpr int A_BYTES  = 128 * ROWB;           // 18432
static constexpr int STAGE_B  = 2 * A_BYTES;          // 36864
static constexpr int GEMM_SMEM = STAGES * STAGE_B;    // 110592

template <bool RELU, bool HOUT>
__global__ __launch_bounds__(128, 2) void gemm_mma_kernel(
    const __nv_bfloat16* __restrict__ Ahi, const __nv_bfloat16* __restrict__ Alo,
    const __nv_bfloat16* __restrict__ Bhi, const __nv_bfloat16* __restrict__ Blo,
    float* __restrict__ C0, float* __restrict__ C1,
    float* __restrict__ C2, float* __restrict__ C3,
    __half* __restrict__ Ch,
    int strideA, int strideB, int nit, int segShift)
{
    extern __shared__ char smem[];
    const uint32_t sbase = smem_u32(smem);
    const int t    = threadIdx.x;
    const int lane = t & 31;
    const int wid  = t >> 5;
    const int wm   = wid >> 1;       // 0..1 -> M offset wm*64
    const int wn   = wid & 1;        // 0..1 -> N offset wn*64
    const int m0   = blockIdx.y * 128;
    const int n0   = blockIdx.x * 128;
    const int cBeg = blockIdx.z * nit;
    const int segMask = (1 << segShift) - 1;

    const __nv_bfloat16* Aseg[3] = { Ahi, Ahi, Alo };
    const __nv_bfloat16* Bseg[3] = { Bhi, Blo, Bhi };

    // cp.async task mapping: 16 tasks/thread (8 A rows + 8 B rows), ch = t&7
    const int rowBase = t >> 3;          // 0..15
    const int ch      = t & 7;
    uint32_t aOffG[8], bOffG[8], sOffA[8];
    #pragma unroll
    for (int i = 0; i < 8; i++) {
        int row = rowBase + 16 * i;
        aOffG[i] = (uint32_t)((m0 + row) * strideA + ch * 8);
        bOffG[i] = (uint32_t)((n0 + row) * strideB + ch * 8);
        sOffA[i] = (uint32_t)(row * ROWB + ch * 16);
    }

    // ldmatrix lane bases (byte offsets within stage)
    const uint32_t aLd = (uint32_t)(wm * 64 + (lane & 15)) * ROWB + (lane >> 4) * 16;
    const uint32_t bLd = A_BYTES +
        (uint32_t)(wn * 64 + ((lane >> 4) & 1) * 8 + (lane & 7)) * ROWB + ((lane >> 3) & 1) * 16;

    float acc[4][8][4];
    #pragma unroll
    for (int f = 0; f < 4; f++)
        #pragma unroll
        for (int j = 0; j < 8; j++)
            #pragma unroll
            for (int e = 0; e < 4; e++) acc[f][j][e] = 0.f;

    auto load_stage = [&](int ci, int s) {
        if (ci < nit) {
            int c   = cBeg + ci;
            int seg = c >> segShift;
            int k0  = (c & segMask) << 6;
            const __nv_bfloat16* ap = Aseg[seg] + k0;
            const __nv_bfloat16* bp = Bseg[seg] + k0;
            uint32_t sb = sbase + s * STAGE_B;
            #pragma unroll
            for (int i = 0; i < 8; i++) cp_async16(sb + sOffA[i], ap + aOffG[i]);
            #pragma unroll
            for (int i = 0; i < 8; i++) cp_async16(sb + A_BYTES + sOffA[i], bp + bOffG[i]);
        }
        cp_commit();
    };

    load_stage(0, 0);
    load_stage(1, 1);

    for (int ci = 0; ci < nit; ci++) {
        cp_wait<STAGES - 2>();
        __syncthreads();
        load_stage(ci + STAGES - 1, (ci + STAGES - 1) % STAGES);

        uint32_t sb = sbase + (ci % STAGES) * STAGE_B;
        #pragma unroll
        for (int ks = 0; ks < 4; ks++) {
            uint32_t a[4][4], b[4][4];
            #pragma unroll
            for (int f = 0; f < 4; f++)
                ldsm_x4(a[f], sb + aLd + f * 16 * ROWB + ks * 32);
            #pragma unroll
            for (int g = 0; g < 4; g++)
                ldsm_x4(b[g], sb + bLd + g * 16 * ROWB + ks * 32);
            #pragma unroll
            for (int f = 0; f < 4; f++)
                #pragma unroll
                for (int g = 0; g < 4; g++) {
                    mma16816(acc[f][2 * g + 0], a[f], &b[g][0]);
                    mma16816(acc[f][2 * g + 1], a[f], &b[g][2]);
                }
        }
    }

    float* C = (blockIdx.z == 0) ? C0 : (blockIdx.z == 1) ? C1
             : (blockIdx.z == 2) ? C2 : C3;
    const int gid = lane >> 2;
    const int tig = lane & 3;
    #pragma unroll
    for (int f = 0; f < 4; f++) {
        int rbase = m0 + wm * 64 + f * 16 + gid;
        #pragma unroll
        for (int j = 0; j < 8; j++) {
            int col = n0 + wn * 64 + j * 8 + tig * 2;
            float2 v0 = { acc[f][j][0], acc[f][j][1] };
            float2 v1 = { acc[f][j][2], acc[f][j][3] };
            if (RELU) {
                v0.x = fmaxf(v0.x, 0.f); v0.y = fmaxf(v0.y, 0.f);
                v1.x = fmaxf(v1.x, 0.f); v1.y = fmaxf(v1.y, 0.f);
            }
            if (HOUT) {
                __half2* Hp = (__half2*)Ch;
                Hp[((size_t)rbase * DIM + col) >> 1]       = __floats2half2_rn(v0.x, v0.y);
                Hp[((size_t)(rbase + 8) * DIM + col) >> 1] = __floats2half2_rn(v1.x, v1.y);
            } else {
                *reinterpret_cast<float2*>(C + (size_t)rbase * DIM + col) = v0;
                *reinterpret_cast<float2*>(C + (size_t)(rbase + 8) * DIM + col) = v1;
            }
        }
    }
}

// ---------------------------------------------------------------------------
// CSR build + gather
// ---------------------------------------------------------------------------
// single block, 1024 threads: exclusive scan of g_degi -> g_rowoff; dis; cursor
__global__ __launch_bounds__(1024) void csr_scan_kernel()
{
    __shared__ int part[1024];
    int t = threadIdx.x;
    int v0 = g_degi[4 * t + 0], v1 = g_degi[4 * t + 1];
    int v2 = g_degi[4 * t + 2], v3 = g_degi[4 * t + 3];
    int s1 = v0 + v1, s2 = s1 + v2, s3 = s2 + v3;
    part[t] = s3;
    __syncthreads();
    #pragma unroll
    for (int off = 1; off < 1024; off <<= 1) {
        int x = (t >= off) ? part[t - off] : 0;
        __syncthreads();
        part[t] += x;
        __syncthreads();
    }
    int base = t ? part[t - 1] : 0;
    g_rowoff[4 * t + 0] = base;
    g_rowoff[4 * t + 1] = base + v0;
    g_rowoff[4 * t + 2] = base + s1;
    g_rowoff[4 * t + 3] = base + s2;
    if (t == 1023) g_rowoff[4096] = base + s3;
    #pragma unroll
    for (int i = 0; i < 4; i++) {
        int n = 4 * t + i;
        int d = g_degi[n];
        g_dis[n] = rsqrtf((float)(d + 1));
        g_cursor[n] = 0;
    }
}
__global__ void csr_place_kernel()
{
    int e = blockIdx.x * blockDim.x + threadIdx.x;
    if (e >= N_EDGES) return;
    int dst = g_dst[e];
    int pos = g_rowoff[dst] + atomicAdd(&g_cursor[dst], 1);
    g_csr[pos] = g_src[e];
}
// one CTA (128 threads, 2 cols each) per dst row, fp16 features:
// Hl[dst] = dis[dst]^2 * XW[dst] + sum_e dis[src]dis[dst] XW[src]
__global__ __launch_bounds__(128) void gather_kernel(float* __restrict__ out)
{
    int dst = blockIdx.x;
    int t   = threadIdx.x;                 // col pair index 0..127
    const __half2* XW = (const __half2*)g_XWh;
    float disD = g_dis[dst];
    float2 sv = __half22float2(XW[(size_t)dst * 128 + t]);
    float accx = sv.x * disD * disD;
    float accy = sv.y * disD * disD;
    int beg = g_rowoff[dst], end = g_rowoff[dst + 1];
    int j = beg;
    for (; j + 1 < end; j += 2) {
        int s0 = g_csr[j], s1 = g_csr[j + 1];
        float w0 = g_dis[s0] * disD, w1 = g_dis[s1] * disD;
        float2 v0 = __half22float2(XW[(size_t)s0 * 128 + t]);
        float2 v1 = __half22float2(XW[(size_t)s1 * 128 + t]);
        accx += v0.x * w0 + v1.x * w1;
        accy += v0.y * w0 + v1.y * w1;
    }
    if (j < end) {
        int s0 = g_csr[j];
        float w0 = g_dis[s0] * disD;
        float2 v0 = __half22float2(XW[(size_t)s0 * 128 + t]);
        accx += v0.x * w0;
        accy += v0.y * w0;
    }
    *reinterpret_cast<float2*>(out + (size_t)dst * DIM + 2 * t) = make_float2(accx, accy);
}
__global__ void combine_kernel(float* __restrict__ out,
                               const float* __restrict__ b,
                               const float* __restrict__ aLp,
                               const float* __restrict__ aHp)
{
    int id = blockIdx.x * blockDim.x + threadIdx.x;
    if (id >= N_NODES * DIM / 4) return;
    float aL = aLp[0], aH = aHp[0];
    int c4 = (id & (DIM / 4 - 1)) << 2;
    float4 hl = reinterpret_cast<const float4*>(out)[id];
    float4 h0 = reinterpret_cast<const float4*>(g_P0)[id];
    float4 h1 = reinterpret_cast<const float4*>(g_P1)[id];
    float4 h2 = reinterpret_cast<const float4*>(g_P2)[id];
    float4 h3 = reinterpret_cast<const float4*>(g_P3)[id];
    float4 bb = *reinterpret_cast<const float4*>(b + c4);
    float4 r;
    r.x = aL * (hl.x + bb.x) + aH * ((h0.x + h1.x) + (h2.x + h3.x));
    r.y = aL * (hl.y + bb.y) + aH * ((h0.y + h1.y) + (h2.y + h3.y));
    r.z = aL * (hl.z + bb.z) + aH * ((h0.z + h1.z) + (h2.z + h3.z));
    r.w = aL * (hl.w + bb.w) + aH * ((h0.w + h1.w) + (h2.w + h3.w));
    reinterpret_cast<float4*>(out)[id] = r;
}

// ---------------------------------------------------------------------------
extern "C" void kernel_launch(void* const* d_in, const int* in_sizes, int n_in,
                              void* d_out, int out_size)
{
    const float* x      = (const float*)d_in[0];
    const void*  ei_raw = d_in[1];
    const float* lap    = (const float*)d_in[2];
    const float* d_inv  = (const float*)d_in[3];
    const float* W_high = (const float*)d_in[4];
    const float* W_conv = (const float*)d_in[5];
    const float* b_conv = (const float*)d_in[6];
    const float* aL     = (const float*)d_in[7];
    const float* aH     = (const float*)d_in[8];
    float*       out    = (float*)d_out;

    float *pA, *pP0, *pP1, *pP2, *pP3;
    cudaGetSymbolAddress((void**)&pA,  g_A);
    cudaGetSymbolAddress((void**)&pP0, g_P0);
    cudaGetSymbolAddress((void**)&pP1, g_P1);
    cudaGetSymbolAddress((void**)&pP2, g_P2);
    cudaGetSymbolAddress((void**)&pP3, g_P3);
    __half* pXWh;
    cudaGetSymbolAddress((void**)&pXWh, g_XWh);
    __nv_bfloat16 *pDh, *pDl, *pLh, *pLl, *pBh, *pBl, *pXh, *pXl, *pWh, *pWl;
    cudaGetSymbolAddress((void**)&pDh, g_dinv_hi);
    cudaGetSymbolAddress((void**)&pDl, g_dinv_lo);
    cudaGetSymbolAddress((void**)&pLh, g_lap_hi);
    cudaGetSymbolAddress((void**)&pLl, g_lap_lo);
    cudaGetSymbolAddress((void**)&pBh, g_Bhi);
    cudaGetSymbolAddress((void**)&pBl, g_Blo);
    cudaGetSymbolAddress((void**)&pXh, g_xhi);
    cudaGetSymbolAddress((void**)&pXl, g_xlo);
    cudaGetSymbolAddress((void**)&pWh, g_Wth);
    cudaGetSymbolAddress((void**)&pWl, g_Wtl);

    cudaFuncSetAttribute(gemm_mma_kernel<false, false>, cudaFuncAttributeMaxDynamicSharedMemorySize, GEMM_SMEM);
    cudaFuncSetAttribute(gemm_mma_kernel<true,  false>, cudaFuncAttributeMaxDynamicSharedMemorySize, GEMM_SMEM);
    cudaFuncSetAttribute(gemm_mma_kernel<false, true >, cudaFuncAttributeMaxDynamicSharedMemorySize, GEMM_SMEM);

    // Edge normalization + CSR build (degree counting fused into convert)
    detect_init_kernel  <<<17, 256>>>((const unsigned int*)ei_raw);
    convert_edges_kernel<<<N_EDGES / 256, 256>>>(ei_raw);
    csr_scan_kernel     <<<1, 1024>>>();
    csr_place_kernel    <<<N_EDGES / 256, 256>>>();

    // Splits of inputs
    int nbig8 = N_NODES * N_NODES / 8;
    split_kernel<<<nbig8 / 256, 256>>>((const float4*)d_inv, (uint4*)pDh, (uint4*)pDl, nbig8);
    split_kernel<<<nbig8 / 256, 256>>>((const float4*)lap,   (uint4*)pLh, (uint4*)pLl, nbig8);
    int nx8 = N_NODES * DIM / 8;
    split_kernel<<<nx8 / 256, 256>>>((const float4*)x, (uint4*)pXh, (uint4*)pXl, nx8);

    dim3 gBig(DIM / 128, N_NODES / 128, 4);  // (2, 32, 4) = 256 CTAs
    dim3 gSm (DIM / 128, N_NODES / 128, 1);  // (2, 32, 1)
    dim3 gTr(N_NODES / 32, DIM / 32);
    dim3 bTr(32, 8);
    dim3 gWt(DIM / 32, DIM / 32);
    const int NIT_BIG = (3 * N_NODES / 64) / 4;   // 48 per z
    const int NIT_SM  = 3 * DIM / 64;             // 12
    const int SEG_BIG = 6;                        // 64 iters / segment
    const int SEG_SM  = 2;                        // 4 iters / segment

    // R = relu(x @ W_high)
    wtranspose_split_kernel<<<gWt, bTr>>>(W_high, pWh, pWl);
    gemm_mma_kernel<true, false><<<gSm, 128, GEMM_SMEM>>>(pXh, pXl, pWh, pWl,
        pA, pA, pA, pA, nullptr, DIM, DIM, NIT_SM, SEG_SM);
    transpose_split_kernel<1><<<gTr, bTr>>>(pA, nullptr, nullptr, nullptr, pBh, pBl);
    // T1 = d_inv @ R
    gemm_mma_kernel<false, false><<<gBig, 128, GEMM_SMEM>>>(pDh, pDl, pBh, pBl,
        pP0, pP1, pP2, pP3, nullptr, N_NODES, N_NODES, NIT_BIG, SEG_BIG);
    // XW_conv = x @ W_conv (fp16, for the gather)
    wtranspose_split_kernel<<<gWt, bTr>>>(W_conv, pWh, pWl);
    gemm_mma_kernel<false, true><<<gSm, 128, GEMM_SMEM>>>(pXh, pXl, pWh, pWl,
        pA, pA, pA, pA, pXWh, DIM, DIM, NIT_SM, SEG_SM);
    // T2 = lap @ T1
    transpose_split_kernel<4><<<gTr, bTr>>>(pP0, pP1, pP2, pP3, pBh, pBl);
    gemm_mma_kernel<false, false><<<gBig, 128, GEMM_SMEM>>>(pLh, pLl, pBh, pBl,
        pP0, pP1, pP2, pP3, nullptr, N_NODES, N_NODES, NIT_BIG, SEG_BIG);
    // Hh = d_inv @ T2 (parts stay in P0..P3)
    transpose_split_kernel<4><<<gTr, bTr>>>(pP0, pP1, pP2, pP3, pBh, pBl);
    gemm_mma_kernel<false, false><<<gBig, 128, GEMM_SMEM>>>(pDh, pDl, pBh, pBl,
        pP0, pP1, pP2, pP3, nullptr, N_NODES, N_NODES, NIT_BIG, SEG_BIG);

    // GCN gather: Hl -> out, then combine
    gather_kernel <<<N_NODES, 128>>>(out);
    int nvec = N_NODES * DIM / 4;
    combine_kernel<<<(nvec + 255) / 256, 256>>>(out, b_conv, aL, aH);
}

// round 11
// speedup vs baseline: 1.3945x; 1.0794x over previous
#include <cuda_runtime.h>
#include <cuda_bf16.h>
#include <cuda_fp16.h>
#include <cstdint>

// FBGCN layer:
//   Hh = d_inv @ (lap @ (d_inv @ relu(x @ W_high)))  -- mma.sync bf16-split GEMMs
//   Hl = GCNConv(x, edge_index, W_conv, b_conv)      -- CSR gather (fp16 features)
//   out = aL*Hl + aH*Hh
// Multi-stream: GCN branch + input splits hidden under the GEMM chain.

static constexpr int N_NODES = 4096;
static constexpr int DIM     = 256;
static constexpr int N_EDGES = 131072;

// fp32 scratch
__device__ __align__(16) float g_A[N_NODES * DIM];    // R
__device__ __align__(16) float g_P0[N_NODES * DIM];   // split-K partials
__device__ __align__(16) float g_P1[N_NODES * DIM];
__device__ __align__(16) float g_P2[N_NODES * DIM];
__device__ __align__(16) float g_P3[N_NODES * DIM];
__device__ __align__(16) __half g_XWh[N_NODES * DIM]; // XW_conv in fp16
__device__ float g_dis[N_NODES];
__device__ int   g_src[N_EDGES];
__device__ int   g_dst[N_EDGES];
__device__ int   g_is64;
// CSR
__device__ int   g_degi[N_NODES];
__device__ int   g_rowoff[N_NODES + 1];
__device__ int   g_cursor[N_NODES];
__device__ int   g_csr[N_EDGES];

// bf16 split buffers
__device__ __align__(128) __nv_bfloat16 g_dinv_hi[N_NODES * N_NODES];
__device__ __align__(128) __nv_bfloat16 g_dinv_lo[N_NODES * N_NODES];
__device__ __align__(128) __nv_bfloat16 g_lap_hi [N_NODES * N_NODES];
__device__ __align__(128) __nv_bfloat16 g_lap_lo [N_NODES * N_NODES];
__device__ __align__(128) __nv_bfloat16 g_Bhi[DIM * N_NODES];   // [256 x 4096] act^T
__device__ __align__(128) __nv_bfloat16 g_Blo[DIM * N_NODES];
__device__ __align__(128) __nv_bfloat16 g_xhi[N_NODES * DIM];   // x splits (K-major rows)
__device__ __align__(128) __nv_bfloat16 g_xlo[N_NODES * DIM];
__device__ __align__(128) __nv_bfloat16 g_Wth[DIM * DIM];       // W_high^T splits
__device__ __align__(128) __nv_bfloat16 g_Wtl[DIM * DIM];
__device__ __align__(128) __nv_bfloat16 g_Wth2[DIM * DIM];      // W_conv^T splits
__device__ __align__(128) __nv_bfloat16 g_Wtl2[DIM * DIM];

// ---------------------------------------------------------------------------
// PTX helpers
// ---------------------------------------------------------------------------
__device__ __forceinline__ uint32_t smem_u32(const void* p) {
    uint32_t a;
    asm("{ .reg .u64 t; cvta.to.shared.u64 t, %1; cvt.u32.u64 %0, t; }" : "=r"(a) : "l"(p));
    return a;
}
__device__ __forceinline__ void cp_async16(uint32_t dst, const void* src) {
    asm volatile("cp.async.cg.shared.global [%0], [%1], 16;" :: "r"(dst), "l"(src) : "memory");
}
__device__ __forceinline__ void cp_commit() { asm volatile("cp.async.commit_group;" ::: "memory"); }
template <int N>
__device__ __forceinline__ void cp_wait() { asm volatile("cp.async.wait_group %0;" :: "n"(N) : "memory"); }

__device__ __forceinline__ void ldsm_x4(uint32_t* r, uint32_t addr) {
    asm volatile("ldmatrix.sync.aligned.m8n8.x4.shared.b16 {%0,%1,%2,%3}, [%4];"
        : "=r"(r[0]), "=r"(r[1]), "=r"(r[2]), "=r"(r[3]) : "r"(addr));
}
__device__ __forceinline__ void mma16816(float* c, const uint32_t* a, const uint32_t* b) {
    asm volatile("mma.sync.aligned.m16n8k16.row.col.f32.bf16.bf16.f32 "
        "{%0,%1,%2,%3}, {%4,%5,%6,%7}, {%8,%9}, {%0,%1,%2,%3};"
        : "+f"(c[0]), "+f"(c[1]), "+f"(c[2]), "+f"(c[3])
        : "r"(a[0]), "r"(a[1]), "r"(a[2]), "r"(a[3]), "r"(b[0]), "r"(b[1]));
}

// ---------------------------------------------------------------------------
// detect dtype + zero degree counters
// ---------------------------------------------------------------------------
__global__ void detect_init_kernel(const unsigned int* __restrict__ raw)
{
    int b = blockIdx.x;
    if (b == 0) {
        if (threadIdx.x == 0) {
            int is64 = 1;
            #pragma unroll 1
            for (int i = 0; i < 128; i++)
                if (raw[2 * i + 1] != 0u) { is64 = 0; break; }
            g_is64 = is64;
        }
    } else {
        g_degi[(b - 1) * 256 + threadIdx.x] = 0;
    }
}
__global__ void convert_edges_kernel(const void* __restrict__ rawp)
{
    int e = blockIdx.x * blockDim.x + threadIdx.x;
    if (e >= N_EDGES) return;
    int s, d;
    if (g_is64) {
        const long long* ei = (const long long*)rawp;
        s = (int)ei[e];
        d = (int)ei[N_EDGES + e];
    } else {
        const int* ei = (const int*)rawp;
        s = ei[e];
        d = ei[N_EDGES + e];
    }
    g_src[e] = s;
    g_dst[e] = d;
    atomicAdd(&g_degi[d], 1);
}

// ---------------------------------------------------------------------------
// fp32 -> (hi, lo) bf16 split, 8 elements per thread
// ---------------------------------------------------------------------------
__global__ void split_kernel(const float4* __restrict__ src,
                             uint4* __restrict__ hi, uint4* __restrict__ lo, int n8)
{
    int id = blockIdx.x * blockDim.x + threadIdx.x;
    if (id >= n8) return;
    float4 a = src[2 * id], b = src[2 * id + 1];
    float f[8] = { a.x, a.y, a.z, a.w, b.x, b.y, b.z, b.w };
    uint32_t H[4], L[4];
    #pragma unroll
    for (int i = 0; i < 4; i++) {
        __nv_bfloat16 h0 = __float2bfloat16(f[2 * i + 0]);
        __nv_bfloat16 h1 = __float2bfloat16(f[2 * i + 1]);
        __nv_bfloat16 l0 = __float2bfloat16(f[2 * i + 0] - __bfloat162float(h0));
        __nv_bfloat16 l1 = __float2bfloat16(f[2 * i + 1] - __bfloat162float(h1));
        __nv_bfloat162 hh(h0, h1), ll(l0, l1);
        H[i] = *(uint32_t*)&hh;
        L[i] = *(uint32_t*)&ll;
    }
    hi[id] = make_uint4(H[0], H[1], H[2], H[3]);
    lo[id] = make_uint4(L[0], L[1], L[2], L[3]);
}

// ---------------------------------------------------------------------------
// activations: fp32 [4096 x 256] (sum of NSUM buffers) -> bf16 splits [256 x 4096]
// ---------------------------------------------------------------------------
template <int NSUM>
__global__ void transpose_split_kernel(const float* __restrict__ s0,
                                       const float* __restrict__ s1,
                                       const float* __restrict__ s2,
                                       const float* __restrict__ s3,
                                       __nv_bfloat16* __restrict__ hi,
                                       __nv_bfloat16* __restrict__ lo)
{
    __shared__ float tile[32][33];
    int k0 = blockIdx.x * 32;
    int n0 = blockIdx.y * 32;
    int tx = threadIdx.x, ty = threadIdx.y;    // 32 x 8
    #pragma unroll
    for (int j = 0; j < 4; j++) {
        size_t o = (size_t)(k0 + ty + j * 8) * DIM + n0 + tx;
        float v = s0[o];
        if (NSUM > 1) v += s1[o];
        if (NSUM > 2) v += s2[o];
        if (NSUM > 3) v += s3[o];
        tile[ty + j * 8][tx] = v;
    }
    __syncthreads();
    #pragma unroll
    for (int j = 0; j < 4; j++) {
        int n = ty + j * 8;
        float v = tile[tx][n];
        __nv_bfloat16 h = __float2bfloat16(v);
        __nv_bfloat16 l = __float2bfloat16(v - __bfloat162float(h));
        size_t o = (size_t)(n0 + n) * N_NODES + k0 + tx;
        hi[o] = h; lo[o] = l;
    }
}

// W [256 x 256] fp32 row-major -> W^T bf16 splits [256 x 256]
__global__ void wtranspose_split_kernel(const float* __restrict__ W,
                                        __nv_bfloat16* __restrict__ hi,
                                        __nv_bfloat16* __restrict__ lo)
{
    __shared__ float tile[32][33];
    int k0 = blockIdx.x * 32;
    int n0 = blockIdx.y * 32;
    int tx = threadIdx.x, ty = threadIdx.y;    // 32 x 8
    #pragma unroll
    for (int j = 0; j < 4; j++)
        tile[ty + j * 8][tx] = W[(size_t)(k0 + ty + j * 8) * DIM + n0 + tx];
    __syncthreads();
    #pragma unroll
    for (int j = 0; j < 4; j++) {
        int n = ty + j * 8;
        float v = tile[tx][n];
        __nv_bfloat16 h = __float2bfloat16(v);
        __nv_bfloat16 l = __float2bfloat16(v - __bfloat162float(h));
        size_t o = (size_t)(n0 + n) * DIM + k0 + tx;
        hi[o] = h; lo[o] = l;
    }
}

// ---------------------------------------------------------------------------
// mma.sync GEMM (R10 config): CTA 128x128, BK=64, 128 threads / 4 warps, warp 64x64.
// ---------------------------------------------------------------------------
static constexpr int STAGES   = 3;
static constexpr int ROWB     = 144;
static constexpr int A_BYTES  = 128 * ROWB;
static constexpr int STAGE_B  = 2 * A_BYTES;
static constexpr int GEMM_SMEM = STAGES * STAGE_B;    // 110592

template <bool RELU, bool HOUT>
__global__ __launch_bounds__(128, 2) void gemm_mma_kernel(
    const __nv_bfloat16* __restrict__ Ahi, const __nv_bfloat16* __restrict__ Alo,
    const __nv_bfloat16* __restrict__ Bhi, const __nv_bfloat16* __restrict__ Blo,
    float* __restrict__ C0, float* __restrict__ C1,
    float* __restrict__ C2, float* __restrict__ C3,
    __half* __restrict__ Ch,
    int strideA, int strideB, int nit, int segShift)
{
    extern __shared__ char smem[];
    const uint32_t sbase = smem_u32(smem);
    const int t    = threadIdx.x;
    const int lane = t & 31;
    const int wid  = t >> 5;
    const int wm   = wid >> 1;
    const int wn   = wid & 1;
    const int m0   = blockIdx.y * 128;
    const int n0   = blockIdx.x * 128;
    const int cBeg = blockIdx.z * nit;
    const int segMask = (1 << segShift) - 1;

    const __nv_bfloat16* Aseg[3] = { Ahi, Ahi, Alo };
    const __nv_bfloat16* Bseg[3] = { Bhi, Blo, Bhi };

    const int rowBase = t >> 3;
    const int ch      = t & 7;
    uint32_t aOffG[8], bOffG[8], sOffA[8];
    #pragma unroll
    for (int i = 0; i < 8; i++) {
        int row = rowBase + 16 * i;
        aOffG[i] = (uint32_t)((m0 + row) * strideA + ch * 8);
        bOffG[i] = (uint32_t)((n0 + row) * strideB + ch * 8);
        sOffA[i] = (uint32_t)(row * ROWB + ch * 16);
    }

    const uint32_t aLd = (uint32_t)(wm * 64 + (lane & 15)) * ROWB + (lane >> 4) * 16;
    const uint32_t bLd = A_BYTES +
        (uint32_t)(wn * 64 + ((lane >> 4) & 1) * 8 + (lane & 7)) * ROWB + ((lane >> 3) & 1) * 16;

    float acc[4][8][4];
    #pragma unroll
    for (int f = 0; f < 4; f++)
        #pragma unroll
        for (int j = 0; j < 8; j++)
            #pragma unroll
            for (int e = 0; e < 4; e++) acc[f][j][e] = 0.f;

    auto load_stage = [&](int ci, int s) {
        if (ci < nit) {
            int c   = cBeg + ci;
            int seg = c >> segShift;
            int k0  = (c & segMask) << 6;
            const __nv_bfloat16* ap = Aseg[seg] + k0;
            const __nv_bfloat16* bp = Bseg[seg] + k0;
            uint32_t sb = sbase + s * STAGE_B;
            #pragma unroll
            for (int i = 0; i < 8; i++) cp_async16(sb + sOffA[i], ap + aOffG[i]);
            #pragma unroll
            for (int i = 0; i < 8; i++) cp_async16(sb + A_BYTES + sOffA[i], bp + bOffG[i]);
        }
        cp_commit();
    };

    load_stage(0, 0);
    load_stage(1, 1);

    for (int ci = 0; ci < nit; ci++) {
        cp_wait<STAGES - 2>();
        __syncthreads();
        load_stage(ci + STAGES - 1, (ci + STAGES - 1) % STAGES);

        uint32_t sb = sbase + (ci % STAGES) * STAGE_B;
        #pragma unroll
        for (int ks = 0; ks < 4; ks++) {
            uint32_t a[4][4], b[4][4];
            #pragma unroll
            for (int f = 0; f < 4; f++)
                ldsm_x4(a[f], sb + aLd + f * 16 * ROWB + ks * 32);
            #pragma unroll
            for (int g = 0; g < 4; g++)
                ldsm_x4(b[g], sb + bLd + g * 16 * ROWB + ks * 32);
            #pragma unroll
            for (int f = 0; f < 4; f++)
                #pragma unroll
                for (int g = 0; g < 4; g++) {
                    mma16816(acc[f][2 * g + 0], a[f], &b[g][0]);
                    mma16816(acc[f][2 * g + 1], a[f], &b[g][2]);
                }
        }
    }

    float* C = (blockIdx.z == 0) ? C0 : (blockIdx.z == 1) ? C1
             : (blockIdx.z == 2) ? C2 : C3;
    const int gid = lane >> 2;
    const int tig = lane & 3;
    #pragma unroll
    for (int f = 0; f < 4; f++) {
        int rbase = m0 + wm * 64 + f * 16 + gid;
        #pragma unroll
        for (int j = 0; j < 8; j++) {
            int col = n0 + wn * 64 + j * 8 + tig * 2;
            float2 v0 = { acc[f][j][0], acc[f][j][1] };
            float2 v1 = { acc[f][j][2], acc[f][j][3] };
            if (RELU) {
                v0.x = fmaxf(v0.x, 0.f); v0.y = fmaxf(v0.y, 0.f);
                v1.x = fmaxf(v1.x, 0.f); v1.y = fmaxf(v1.y, 0.f);
            }
            if (HOUT) {
                __half2* Hp = (__half2*)Ch;
                Hp[((size_t)rbase * DIM + col) >> 1]       = __floats2half2_rn(v0.x, v0.y);
                Hp[((size_t)(rbase + 8) * DIM + col) >> 1] = __floats2half2_rn(v1.x, v1.y);
            } else {
                *reinterpret_cast<float2*>(C + (size_t)rbase * DIM + col) = v0;
                *reinterpret_cast<float2*>(C + (size_t)(rbase + 8) * DIM + col) = v1;
            }
        }
    }
}

// ---------------------------------------------------------------------------
// CSR build
// ---------------------------------------------------------------------------
__global__ __launch_bounds__(1024) void csr_scan_kernel()
{
    __shared__ int part[1024];
    int t = threadIdx.x;
    int v0 = g_degi[4 * t + 0], v1 = g_degi[4 * t + 1];
    int v2 = g_degi[4 * t + 2], v3 = g_degi[4 * t + 3];
    int s1 = v0 + v1, s2 = s1 + v2, s3 = s2 + v3;
    part[t] = s3;
    __syncthreads();
    #pragma unroll
    for (int off = 1; off < 1024; off <<= 1) {
        int x = (t >= off) ? part[t - off] : 0;
        __syncthreads();
        part[t] += x;
        __syncthreads();
    }
    int base = t ? part[t - 1] : 0;
    g_rowoff[4 * t + 0] = base;
    g_rowoff[4 * t + 1] = base + v0;
    g_rowoff[4 * t + 2] = base + s1;
    g_rowoff[4 * t + 3] = base + s2;
    if (t == 1023) g_rowoff[4096] = base + s3;
    #pragma unroll
    for (int i = 0; i < 4; i++) {
        int n = 4 * t + i;
        int d = g_degi[n];
        g_dis[n] = rsqrtf((float)(d + 1));
        g_cursor[n] = 0;
    }
}
__global__ void csr_place_kernel()
{
    int e = blockIdx.x * blockDim.x + threadIdx.x;
    if (e >= N_EDGES) return;
    int dst = g_dst[e];
    int pos = g_rowoff[dst] + atomicAdd(&g_cursor[dst], 1);
    g_csr[pos] = g_src[e];
}

// ---------------------------------------------------------------------------
// Fused gather + combine: one CTA (128 threads) per dst row.
// out[dst] = aL*(Hl[dst] + b) + aH*(P0+P1+P2+P3)[dst]
// ---------------------------------------------------------------------------
__global__ __launch_bounds__(128) void gather_combine_kernel(
    float* __restrict__ out, const float* __restrict__ b,
    const float* __restrict__ aLp, const float* __restrict__ aHp)
{
    int dst = blockIdx.x;
    int t   = threadIdx.x;                 // col pair index 0..127
    const __half2* XW = (const __half2*)g_XWh;
    float disD = g_dis[dst];
    float2 sv = __half22float2(XW[(size_t)dst * 128 + t]);
    float accx = sv.x * disD * disD;
    float accy = sv.y * disD * disD;
    int beg = g_rowoff[dst], end = g_rowoff[dst + 1];
    int j = beg;
    for (; j + 1 < end; j += 2) {
        int s0 = g_csr[j], s1 = g_csr[j + 1];
        float w0 = g_dis[s0] * disD, w1 = g_dis[s1] * disD;
        float2 v0 = __half22float2(XW[(size_t)s0 * 128 + t]);
        float2 v1 = __half22float2(XW[(size_t)s1 * 128 + t]);
        accx += v0.x * w0 + v1.x * w1;
        accy += v0.y * w0 + v1.y * w1;
    }
    if (j < end) {
        int s0 = g_csr[j];
        float w0 = g_dis[s0] * disD;
        float2 v0 = __half22float2(XW[(size_t)s0 * 128 + t]);
        accx += v0.x * w0;
        accy += v0.y * w0;
    }
    float aL = aLp[0], aH = aHp[0];
    size_t o2 = (size_t)dst * 128 + t;     // float2 index
    float2 h0 = reinterpret_cast<const float2*>(g_P0)[o2];
    float2 h1 = reinterpret_cast<const float2*>(g_P1)[o2];
    float2 h2 = reinterpret_cast<const float2*>(g_P2)[o2];
    float2 h3 = reinterpret_cast<const float2*>(g_P3)[o2];
    float2 bb = *reinterpret_cast<const float2*>(b + 2 * t);
    float2 r;
    r.x = aL * (accx + bb.x) + aH * ((h0.x + h1.x) + (h2.x + h3.x));
    r.y = aL * (accy + bb.y) + aH * ((h0.y + h1.y) + (h2.y + h3.y));
    *reinterpret_cast<float2*>(out + (size_t)dst * DIM + 2 * t) = r;
}

// ---------------------------------------------------------------------------
extern "C" void kernel_launch(void* const* d_in, const int* in_sizes, int n_in,
                              void* d_out, int out_size)
{
    const float* x      = (const float*)d_in[0];
    const void*  ei_raw = d_in[1];
    const float* lap    = (const float*)d_in[2];
    const float* d_inv  = (const float*)d_in[3];
    const float* W_high = (const float*)d_in[4];
    const float* W_conv = (const float*)d_in[5];
    const float* b_conv = (const float*)d_in[6];
    const float* aL     = (const float*)d_in[7];
    const float* aH     = (const float*)d_in[8];
    float*       out    = (float*)d_out;

    float *pA, *pP0, *pP1, *pP2, *pP3;
    cudaGetSymbolAddress((void**)&pA,  g_A);
    cudaGetSymbolAddress((void**)&pP0, g_P0);
    cudaGetSymbolAddress((void**)&pP1, g_P1);
    cudaGetSymbolAddress((void**)&pP2, g_P2);
    cudaGetSymbolAddress((void**)&pP3, g_P3);
    __half* pXWh;
    cudaGetSymbolAddress((void**)&pXWh, g_XWh);
    __nv_bfloat16 *pDh, *pDl, *pLh, *pLl, *pBh, *pBl, *pXh, *pXl, *pWh, *pWl, *pWh2, *pWl2;
    cudaGetSymbolAddress((void**)&pDh, g_dinv_hi);
    cudaGetSymbolAddress((void**)&pDl, g_dinv_lo);
    cudaGetSymbolAddress((void**)&pLh, g_lap_hi);
    cudaGetSymbolAddress((void**)&pLl, g_lap_lo);
    cudaGetSymbolAddress((void**)&pBh, g_Bhi);
    cudaGetSymbolAddress((void**)&pBl, g_Blo);
    cudaGetSymbolAddress((void**)&pXh, g_xhi);
    cudaGetSymbolAddress((void**)&pXl, g_xlo);
    cudaGetSymbolAddress((void**)&pWh, g_Wth);
    cudaGetSymbolAddress((void**)&pWl, g_Wtl);
    cudaGetSymbolAddress((void**)&pWh2, g_Wth2);
    cudaGetSymbolAddress((void**)&pWl2, g_Wtl2);

    cudaFuncSetAttribute(gemm_mma_kernel<false, false>, cudaFuncAttributeMaxDynamicSharedMemorySize, GEMM_SMEM);
    cudaFuncSetAttribute(gemm_mma_kernel<true,  false>, cudaFuncAttributeMaxDynamicSharedMemorySize, GEMM_SMEM);
    cudaFuncSetAttribute(gemm_mma_kernel<false, true >, cudaFuncAttributeMaxDynamicSharedMemorySize, GEMM_SMEM);

    // Streams + events (created per call; host-side resources, no device alloc)
    cudaStream_t s1, s2;
    cudaStreamCreateWithFlags(&s1, cudaStreamNonBlocking);
    cudaStreamCreateWithFlags(&s2, cudaStreamNonBlocking);
    cudaEvent_t E0, Ex, Ed, El, Eg;
    cudaEventCreateWithFlags(&E0, cudaEventDisableTiming);
    cudaEventCreateWithFlags(&Ex, cudaEventDisableTiming);
    cudaEventCreateWithFlags(&Ed, cudaEventDisableTiming);
    cudaEventCreateWithFlags(&El, cudaEventDisableTiming);
    cudaEventCreateWithFlags(&Eg, cudaEventDisableTiming);

    dim3 gBig(DIM / 128, N_NODES / 128, 4);  // (2, 32, 4) = 256 CTAs
    dim3 gSm (DIM / 128, N_NODES / 128, 1);
    dim3 gTr(N_NODES / 32, DIM / 32);
    dim3 bTr(32, 8);
    dim3 gWt(DIM / 32, DIM / 32);
    const int NIT_BIG = (3 * N_NODES / 64) / 4;   // 48 per z
    const int NIT_SM  = 3 * DIM / 64;             // 12
    const int SEG_BIG = 6;
    const int SEG_SM  = 2;
    int nbig8 = N_NODES * N_NODES / 8;
    int nx8   = N_NODES * DIM / 8;

    // ---- fork ----
    cudaEventRecord(E0, 0);
    cudaStreamWaitEvent(s1, E0, 0);
    cudaStreamWaitEvent(s2, E0, 0);

    // s1: big matrix splits (gating events for GEMM1 / GEMM2)
    split_kernel<<<nbig8 / 256, 256, 0, s1>>>((const float4*)d_inv, (uint4*)pDh, (uint4*)pDl, nbig8);
    cudaEventRecord(Ed, s1);
    split_kernel<<<nbig8 / 256, 256, 0, s1>>>((const float4*)lap, (uint4*)pLh, (uint4*)pLl, nbig8);
    cudaEventRecord(El, s1);

    // s2: edge conversion + CSR + W_conv transpose (XW_conv GEMM after Ex)
    detect_init_kernel  <<<17, 256, 0, s2>>>((const unsigned int*)ei_raw);
    convert_edges_kernel<<<N_EDGES / 256, 256, 0, s2>>>(ei_raw);
    csr_scan_kernel     <<<1, 1024, 0, s2>>>();
    csr_place_kernel    <<<N_EDGES / 256, 256, 0, s2>>>();
    wtranspose_split_kernel<<<gWt, bTr, 0, s2>>>(W_conv, pWh2, pWl2);

    // s0: critical path start
    wtranspose_split_kernel<<<gWt, bTr>>>(W_high, pWh, pWl);
    split_kernel<<<nx8 / 256, 256>>>((const float4*)x, (uint4*)pXh, (uint4*)pXl, nx8);
    cudaEventRecord(Ex, 0);

    // s2 continues: XW_conv = x @ W_conv (fp16 out)
    cudaStreamWaitEvent(s2, Ex, 0);
    gemm_mma_kernel<false, true><<<gSm, 128, GEMM_SMEM, s2>>>(pXh, pXl, pWh2, pWl2,
        pA, pA, pA, pA, pXWh, DIM, DIM, NIT_SM, SEG_SM);
    cudaEventRecord(Eg, s2);

    // s0: R = relu(x @ W_high); transpose-split
    gemm_mma_kernel<true, false><<<gSm, 128, GEMM_SMEM>>>(pXh, pXl, pWh, pWl,
        pA, pA, pA, pA, nullptr, DIM, DIM, NIT_SM, SEG_SM);
    transpose_split_kernel<1><<<gTr, bTr>>>(pA, nullptr, nullptr, nullptr, pBh, pBl);
    // T1 = d_inv @ R
    cudaStreamWaitEvent(0, Ed, 0);
    gemm_mma_kernel<false, false><<<gBig, 128, GEMM_SMEM>>>(pDh, pDl, pBh, pBl,
        pP0, pP1, pP2, pP3, nullptr, N_NODES, N_NODES, NIT_BIG, SEG_BIG);
    // T2 = lap @ T1
    transpose_split_kernel<4><<<gTr, bTr>>>(pP0, pP1, pP2, pP3, pBh, pBl);
    cudaStreamWaitEvent(0, El, 0);
    gemm_mma_kernel<false, false><<<gBig, 128, GEMM_SMEM>>>(pLh, pLl, pBh, pBl,
        pP0, pP1, pP2, pP3, nullptr, N_NODES, N_NODES, NIT_BIG, SEG_BIG);
    // Hh = d_inv @ T2
    transpose_split_kernel<4><<<gTr, bTr>>>(pP0, pP1, pP2, pP3, pBh, pBl);
    gemm_mma_kernel<false, false><<<gBig, 128, GEMM_SMEM>>>(pDh, pDl, pBh, pBl,
        pP0, pP1, pP2, pP3, nullptr, N_NODES, N_NODES, NIT_BIG, SEG_BIG);

    // join GCN branch, fused gather + combine
    cudaStreamWaitEvent(0, Eg, 0);
    gather_combine_kernel<<<N_NODES, 128>>>(out, b_conv, aL, aH);

    // cleanup host-side handles (after all work enqueued; events/streams are
    // reference-counted by the graph, destroy is deferred-safe)
    cudaEventDestroy(E0); cudaEventDestroy(Ex); cudaEventDestroy(Ed);
    cudaEventDestroy(El); cudaEventDestroy(Eg);
    cudaStreamDestroy(s1); cudaStreamDestroy(s2);
}

// round 12
// speedup vs baseline: 1.4204x; 1.0186x over previous
#include <cuda_runtime.h>
#include <cuda_bf16.h>
#include <cuda_fp16.h>
#include <cstdint>

// FBGCN layer:
//   Hh = d_inv @ (lap @ (d_inv @ relu(x @ W_high)))  -- mma.sync bf16-split GEMMs
//   Hl = GCNConv(x, edge_index, W_conv, b_conv)      -- CSR gather (fp16 features)
//   out = aL*Hl + aH*Hh
// Multi-stream: GCN branch + input splits hidden under the GEMM chain.
// R^T computed directly by GEMM with fused bf16-split epilogue (no transpose).

static constexpr int N_NODES = 4096;
static constexpr int DIM     = 256;
static constexpr int N_EDGES = 131072;

// fp32 scratch
__device__ __align__(16) float g_A[N_NODES * DIM];    // Hl
__device__ __align__(16) float g_P0[N_NODES * DIM];   // split-K partials
__device__ __align__(16) float g_P1[N_NODES * DIM];
__device__ __align__(16) float g_P2[N_NODES * DIM];
__device__ __align__(16) float g_P3[N_NODES * DIM];
__device__ __align__(16) __half g_XWh[N_NODES * DIM]; // XW_conv in fp16
__device__ float g_dis[N_NODES];
__device__ int   g_src[N_EDGES];
__device__ int   g_dst[N_EDGES];
__device__ int   g_is64;
// CSR
__device__ int   g_degi[N_NODES];
__device__ int   g_rowoff[N_NODES + 1];
__device__ int   g_cursor[N_NODES];
__device__ int   g_csr[N_EDGES];

// bf16 split buffers
__device__ __align__(128) __nv_bfloat16 g_dinv_hi[N_NODES * N_NODES];
__device__ __align__(128) __nv_bfloat16 g_dinv_lo[N_NODES * N_NODES];
__device__ __align__(128) __nv_bfloat16 g_lap_hi [N_NODES * N_NODES];
__device__ __align__(128) __nv_bfloat16 g_lap_lo [N_NODES * N_NODES];
__device__ __align__(128) __nv_bfloat16 g_Bhi[DIM * N_NODES];   // [256 x 4096] act^T
__device__ __align__(128) __nv_bfloat16 g_Blo[DIM * N_NODES];
__device__ __align__(128) __nv_bfloat16 g_xhi[N_NODES * DIM];   // x splits (K-major rows)
__device__ __align__(128) __nv_bfloat16 g_xlo[N_NODES * DIM];
__device__ __align__(128) __nv_bfloat16 g_Wth[DIM * DIM];       // W_high^T splits
__device__ __align__(128) __nv_bfloat16 g_Wtl[DIM * DIM];
__device__ __align__(128) __nv_bfloat16 g_Wth2[DIM * DIM];      // W_conv^T splits
__device__ __align__(128) __nv_bfloat16 g_Wtl2[DIM * DIM];

// ---------------------------------------------------------------------------
// PTX helpers
// ---------------------------------------------------------------------------
__device__ __forceinline__ uint32_t smem_u32(const void* p) {
    uint32_t a;
    asm("{ .reg .u64 t; cvta.to.shared.u64 t, %1; cvt.u32.u64 %0, t; }" : "=r"(a) : "l"(p));
    return a;
}
__device__ __forceinline__ void cp_async16(uint32_t dst, const void* src) {
    asm volatile("cp.async.cg.shared.global [%0], [%1], 16;" :: "r"(dst), "l"(src) : "memory");
}
__device__ __forceinline__ void cp_commit() { asm volatile("cp.async.commit_group;" ::: "memory"); }
template <int N>
__device__ __forceinline__ void cp_wait() { asm volatile("cp.async.wait_group %0;" :: "n"(N) : "memory"); }

__device__ __forceinline__ void ldsm_x4(uint32_t* r, uint32_t addr) {
    asm volatile("ldmatrix.sync.aligned.m8n8.x4.shared.b16 {%0,%1,%2,%3}, [%4];"
        : "=r"(r[0]), "=r"(r[1]), "=r"(r[2]), "=r"(r[3]) : "r"(addr));
}
__device__ __forceinline__ void mma16816(float* c, const uint32_t* a, const uint32_t* b) {
    asm volatile("mma.sync.aligned.m16n8k16.row.col.f32.bf16.bf16.f32 "
        "{%0,%1,%2,%3}, {%4,%5,%6,%7}, {%8,%9}, {%0,%1,%2,%3};"
        : "+f"(c[0]), "+f"(c[1]), "+f"(c[2]), "+f"(c[3])
        : "r"(a[0]), "r"(a[1]), "r"(a[2]), "r"(a[3]), "r"(b[0]), "r"(b[1]));
}

// ---------------------------------------------------------------------------
// detect dtype + zero degree counters
// ---------------------------------------------------------------------------
__global__ void detect_init_kernel(const unsigned int* __restrict__ raw)
{
    int b = blockIdx.x;
    if (b == 0) {
        if (threadIdx.x == 0) {
            int is64 = 1;
            #pragma unroll 1
            for (int i = 0; i < 128; i++)
                if (raw[2 * i + 1] != 0u) { is64 = 0; break; }
            g_is64 = is64;
        }
    } else {
        g_degi[(b - 1) * 256 + threadIdx.x] = 0;
    }
}
__global__ void convert_edges_kernel(const void* __restrict__ rawp)
{
    int e = blockIdx.x * blockDim.x + threadIdx.x;
    if (e >= N_EDGES) return;
    int s, d;
    if (g_is64) {
        const long long* ei = (const long long*)rawp;
        s = (int)ei[e];
        d = (int)ei[N_EDGES + e];
    } else {
        const int* ei = (const int*)rawp;
        s = ei[e];
        d = ei[N_EDGES + e];
    }
    g_src[e] = s;
    g_dst[e] = d;
    atomicAdd(&g_degi[d], 1);
}

// ---------------------------------------------------------------------------
// fp32 -> (hi, lo) bf16 split, 8 elements per thread
// ---------------------------------------------------------------------------
__global__ void split_kernel(const float4* __restrict__ src,
                             uint4* __restrict__ hi, uint4* __restrict__ lo, int n8)
{
    int id = blockIdx.x * blockDim.x + threadIdx.x;
    if (id >= n8) return;
    float4 a = src[2 * id], b = src[2 * id + 1];
    float f[8] = { a.x, a.y, a.z, a.w, b.x, b.y, b.z, b.w };
    uint32_t H[4], L[4];
    #pragma unroll
    for (int i = 0; i < 4; i++) {
        __nv_bfloat16 h0 = __float2bfloat16(f[2 * i + 0]);
        __nv_bfloat16 h1 = __float2bfloat16(f[2 * i + 1]);
        __nv_bfloat16 l0 = __float2bfloat16(f[2 * i + 0] - __bfloat162float(h0));
        __nv_bfloat16 l1 = __float2bfloat16(f[2 * i + 1] - __bfloat162float(h1));
        __nv_bfloat162 hh(h0, h1), ll(l0, l1);
        H[i] = *(uint32_t*)&hh;
        L[i] = *(uint32_t*)&ll;
    }
    hi[id] = make_uint4(H[0], H[1], H[2], H[3]);
    lo[id] = make_uint4(L[0], L[1], L[2], L[3]);
}

// ---------------------------------------------------------------------------
// activations: fp32 [4096 x 256] (sum of 4 buffers) -> bf16 splits [256 x 4096]
// ---------------------------------------------------------------------------
__global__ void transpose_split_kernel(const float* __restrict__ s0,
                                       const float* __restrict__ s1,
                                       const float* __restrict__ s2,
                                       const float* __restrict__ s3,
                                       __nv_bfloat16* __restrict__ hi,
                                       __nv_bfloat16* __restrict__ lo)
{
    __shared__ float tile[32][33];
    int k0 = blockIdx.x * 32;
    int n0 = blockIdx.y * 32;
    int tx = threadIdx.x, ty = threadIdx.y;    // 32 x 8
    #pragma unroll
    for (int j = 0; j < 4; j++) {
        size_t o = (size_t)(k0 + ty + j * 8) * DIM + n0 + tx;
        float v = (s0[o] + s1[o]) + (s2[o] + s3[o]);
        tile[ty + j * 8][tx] = v;
    }
    __syncthreads();
    #pragma unroll
    for (int j = 0; j < 4; j++) {
        int n = ty + j * 8;
        float v = tile[tx][n];
        __nv_bfloat16 h = __float2bfloat16(v);
        __nv_bfloat16 l = __float2bfloat16(v - __bfloat162float(h));
        size_t o = (size_t)(n0 + n) * N_NODES + k0 + tx;
        hi[o] = h; lo[o] = l;
    }
}

// W [256 x 256] fp32 row-major -> W^T bf16 splits [256 x 256]
__global__ void wtranspose_split_kernel(const float* __restrict__ W,
                                        __nv_bfloat16* __restrict__ hi,
                                        __nv_bfloat16* __restrict__ lo)
{
    __shared__ float tile[32][33];
    int k0 = blockIdx.x * 32;
    int n0 = blockIdx.y * 32;
    int tx = threadIdx.x, ty = threadIdx.y;    // 32 x 8
    #pragma unroll
    for (int j = 0; j < 4; j++)
        tile[ty + j * 8][tx] = W[(size_t)(k0 + ty + j * 8) * DIM + n0 + tx];
    __syncthreads();
    #pragma unroll
    for (int j = 0; j < 4; j++) {
        int n = ty + j * 8;
        float v = tile[tx][n];
        __nv_bfloat16 h = __float2bfloat16(v);
        __nv_bfloat16 l = __float2bfloat16(v - __bfloat162float(h));
        size_t o = (size_t)(n0 + n) * DIM + k0 + tx;
        hi[o] = h; lo[o] = l;
    }
}

// ---------------------------------------------------------------------------
// mma.sync GEMM: CTA 128x128, BK=64, 128 threads / 4 warps, warp 64x64.
// OUT_MODE 0: fp32 to C0..C3 (per blockIdx.z), stride strideC
//          1: fp16 (half2) to Ch, stride strideC
//          2: bf16 hi/lo split to Bh/Bl, stride strideC (+optional RELU)
// ---------------------------------------------------------------------------
static constexpr int STAGES   = 3;
static constexpr int ROWB     = 144;
static constexpr int A_BYTES  = 128 * ROWB;
static constexpr int STAGE_B  = 2 * A_BYTES;
static constexpr int GEMM_SMEM = STAGES * STAGE_B;    // 110592

template <bool RELU, int OUT_MODE>
__global__ __launch_bounds__(128, 2) void gemm_mma_kernel(
    const __nv_bfloat16* __restrict__ Ahi, const __nv_bfloat16* __restrict__ Alo,
    const __nv_bfloat16* __restrict__ Bhi, const __nv_bfloat16* __restrict__ Blo,
    float* __restrict__ C0, float* __restrict__ C1,
    float* __restrict__ C2, float* __restrict__ C3,
    __half* __restrict__ Ch,
    __nv_bfloat16* __restrict__ Bh, __nv_bfloat16* __restrict__ Bl,
    int strideA, int strideB, int strideC, int nit, int segShift)
{
    extern __shared__ char smem[];
    const uint32_t sbase = smem_u32(smem);
    const int t    = threadIdx.x;
    const int lane = t & 31;
    const int wid  = t >> 5;
    const int wm   = wid >> 1;
    const int wn   = wid & 1;
    const int m0   = blockIdx.y * 128;
    const int n0   = blockIdx.x * 128;
    const int cBeg = blockIdx.z * nit;
    const int segMask = (1 << segShift) - 1;

    const __nv_bfloat16* Aseg[3] = { Ahi, Ahi, Alo };
    const __nv_bfloat16* Bseg[3] = { Bhi, Blo, Bhi };

    const int rowBase = t >> 3;
    const int ch      = t & 7;
    uint32_t aOffG[8], bOffG[8], sOffA[8];
    #pragma unroll
    for (int i = 0; i < 8; i++) {
        int row = rowBase + 16 * i;
        aOffG[i] = (uint32_t)((m0 + row) * strideA + ch * 8);
        bOffG[i] = (uint32_t)((n0 + row) * strideB + ch * 8);
        sOffA[i] = (uint32_t)(row * ROWB + ch * 16);
    }

    const uint32_t aLd = (uint32_t)(wm * 64 + (lane & 15)) * ROWB + (lane >> 4) * 16;
    const uint32_t bLd = A_BYTES +
        (uint32_t)(wn * 64 + ((lane >> 4) & 1) * 8 + (lane & 7)) * ROWB + ((lane >> 3) & 1) * 16;

    float acc[4][8][4];
    #pragma unroll
    for (int f = 0; f < 4; f++)
        #pragma unroll
        for (int j = 0; j < 8; j++)
            #pragma unroll
            for (int e = 0; e < 4; e++) acc[f][j][e] = 0.f;

    auto load_stage = [&](int ci, int s) {
        if (ci < nit) {
            int c   = cBeg + ci;
            int seg = c >> segShift;
            int k0  = (c & segMask) << 6;
            const __nv_bfloat16* ap = Aseg[seg] + k0;
            const __nv_bfloat16* bp = Bseg[seg] + k0;
            uint32_t sb = sbase + s * STAGE_B;
            #pragma unroll
            for (int i = 0; i < 8; i++) cp_async16(sb + sOffA[i], ap + aOffG[i]);
            #pragma unroll
            for (int i = 0; i < 8; i++) cp_async16(sb + A_BYTES + sOffA[i], bp + bOffG[i]);
        }
        cp_commit();
    };

    load_stage(0, 0);
    load_stage(1, 1);

    for (int ci = 0; ci < nit; ci++) {
        cp_wait<STAGES - 2>();
        __syncthreads();
        load_stage(ci + STAGES - 1, (ci + STAGES - 1) % STAGES);

        uint32_t sb = sbase + (ci % STAGES) * STAGE_B;
        #pragma unroll
        for (int ks = 0; ks < 4; ks++) {
            uint32_t a[4][4], b[4][4];
            #pragma unroll
            for (int f = 0; f < 4; f++)
                ldsm_x4(a[f], sb + aLd + f * 16 * ROWB + ks * 32);
            #pragma unroll
            for (int g = 0; g < 4; g++)
                ldsm_x4(b[g], sb + bLd + g * 16 * ROWB + ks * 32);
            #pragma unroll
            for (int f = 0; f < 4; f++)
                #pragma unroll
                for (int g = 0; g < 4; g++) {
                    mma16816(acc[f][2 * g + 0], a[f], &b[g][0]);
                    mma16816(acc[f][2 * g + 1], a[f], &b[g][2]);
                }
        }
    }

    float* C = (blockIdx.z == 0) ? C0 : (blockIdx.z == 1) ? C1
             : (blockIdx.z == 2) ? C2 : C3;
    const int gid = lane >> 2;
    const int tig = lane & 3;
    #pragma unroll
    for (int f = 0; f < 4; f++) {
        int rbase = m0 + wm * 64 + f * 16 + gid;
        #pragma unroll
        for (int j = 0; j < 8; j++) {
            int col = n0 + wn * 64 + j * 8 + tig * 2;
            float2 v0 = { acc[f][j][0], acc[f][j][1] };
            float2 v1 = { acc[f][j][2], acc[f][j][3] };
            if (RELU) {
                v0.x = fmaxf(v0.x, 0.f); v0.y = fmaxf(v0.y, 0.f);
                v1.x = fmaxf(v1.x, 0.f); v1.y = fmaxf(v1.y, 0.f);
            }
            size_t o0 = (size_t)rbase * strideC + col;
            size_t o1 = (size_t)(rbase + 8) * strideC + col;
            if (OUT_MODE == 1) {
                __half2* Hp = (__half2*)Ch;
                Hp[o0 >> 1] = __floats2half2_rn(v0.x, v0.y);
                Hp[o1 >> 1] = __floats2half2_rn(v1.x, v1.y);
            } else if (OUT_MODE == 2) {
                __nv_bfloat16 h0 = __float2bfloat16(v0.x);
                __nv_bfloat16 h1 = __float2bfloat16(v0.y);
                __nv_bfloat16 l0 = __float2bfloat16(v0.x - __bfloat162float(h0));
                __nv_bfloat16 l1 = __float2bfloat16(v0.y - __bfloat162float(h1));
                *reinterpret_cast<__nv_bfloat162*>(Bh + o0) = __nv_bfloat162(h0, h1);
                *reinterpret_cast<__nv_bfloat162*>(Bl + o0) = __nv_bfloat162(l0, l1);
                __nv_bfloat16 h2 = __float2bfloat16(v1.x);
                __nv_bfloat16 h3 = __float2bfloat16(v1.y);
                __nv_bfloat16 l2 = __float2bfloat16(v1.x - __bfloat162float(h2));
                __nv_bfloat16 l3 = __float2bfloat16(v1.y - __bfloat162float(h3));
                *reinterpret_cast<__nv_bfloat162*>(Bh + o1) = __nv_bfloat162(h2, h3);
                *reinterpret_cast<__nv_bfloat162*>(Bl + o1) = __nv_bfloat162(l2, l3);
            } else {
                *reinterpret_cast<float2*>(C + o0) = v0;
                *reinterpret_cast<float2*>(C + o1) = v1;
            }
        }
    }
}

// ---------------------------------------------------------------------------
// CSR build
// ---------------------------------------------------------------------------
__global__ __launch_bounds__(1024) void csr_scan_kernel()
{
    __shared__ int part[1024];
    int t = threadIdx.x;
    int v0 = g_degi[4 * t + 0], v1 = g_degi[4 * t + 1];
    int v2 = g_degi[4 * t + 2], v3 = g_degi[4 * t + 3];
    int s1 = v0 + v1, s2 = s1 + v2, s3 = s2 + v3;
    part[t] = s3;
    __syncthreads();
    #pragma unroll
    for (int off = 1; off < 1024; off <<= 1) {
        int x = (t >= off) ? part[t - off] : 0;
        __syncthreads();
        part[t] += x;
        __syncthreads();
    }
    int base = t ? part[t - 1] : 0;
    g_rowoff[4 * t + 0] = base;
    g_rowoff[4 * t + 1] = base + v0;
    g_rowoff[4 * t + 2] = base + s1;
    g_rowoff[4 * t + 3] = base + s2;
    if (t == 1023) g_rowoff[4096] = base + s3;
    #pragma unroll
    for (int i = 0; i < 4; i++) {
        int n = 4 * t + i;
        int d = g_degi[n];
        g_dis[n] = rsqrtf((float)(d + 1));
        g_cursor[n] = 0;
    }
}
__global__ void csr_place_kernel()
{
    int e = blockIdx.x * blockDim.x + threadIdx.x;
    if (e >= N_EDGES) return;
    int dst = g_dst[e];
    int pos = g_rowoff[dst] + atomicAdd(&g_cursor[dst], 1);
    g_csr[pos] = g_src[e];
}

// ---------------------------------------------------------------------------
// Gather: Hl[dst] -> g_A (runs on side stream, hidden under GEMM chain)
// ---------------------------------------------------------------------------
__global__ __launch_bounds__(128) void gather_kernel()
{
    int dst = blockIdx.x;
    int t   = threadIdx.x;                 // col pair index 0..127
    const __half2* XW = (const __half2*)g_XWh;
    float disD = g_dis[dst];
    float2 sv = __half22float2(XW[(size_t)dst * 128 + t]);
    float accx = sv.x * disD * disD;
    float accy = sv.y * disD * disD;
    int beg = g_rowoff[dst], end = g_rowoff[dst + 1];
    int j = beg;
    for (; j + 1 < end; j += 2) {
        int s0 = g_csr[j], s1 = g_csr[j + 1];
        float w0 = g_dis[s0] * disD, w1 = g_dis[s1] * disD;
        float2 v0 = __half22float2(XW[(size_t)s0 * 128 + t]);
        float2 v1 = __half22float2(XW[(size_t)s1 * 128 + t]);
        accx += v0.x * w0 + v1.x * w1;
        accy += v0.y * w0 + v1.y * w1;
    }
    if (j < end) {
        int s0 = g_csr[j];
        float w0 = g_dis[s0] * disD;
        float2 v0 = __half22float2(XW[(size_t)s0 * 128 + t]);
        accx += v0.x * w0;
        accy += v0.y * w0;
    }
    *reinterpret_cast<float2*>(g_A + (size_t)dst * DIM + 2 * t) = make_float2(accx, accy);
}

// out = aL*(Hl + b) + aH*(P0+P1+P2+P3)
__global__ void combine_kernel(float* __restrict__ out,
                               const float* __restrict__ b,
                               const float* __restrict__ aLp,
                               const float* __restrict__ aHp)
{
    int id = blockIdx.x * blockDim.x + threadIdx.x;
    if (id >= N_NODES * DIM / 4) return;
    float aL = aLp[0], aH = aHp[0];
    int c4 = (id & (DIM / 4 - 1)) << 2;
    float4 hl = reinterpret_cast<const float4*>(g_A)[id];
    float4 h0 = reinterpret_cast<const float4*>(g_P0)[id];
    float4 h1 = reinterpret_cast<const float4*>(g_P1)[id];
    float4 h2 = reinterpret_cast<const float4*>(g_P2)[id];
    float4 h3 = reinterpret_cast<const float4*>(g_P3)[id];
    float4 bb = *reinterpret_cast<const float4*>(b + c4);
    float4 r;
    r.x = aL * (hl.x + bb.x) + aH * ((h0.x + h1.x) + (h2.x + h3.x));
    r.y = aL * (hl.y + bb.y) + aH * ((h0.y + h1.y) + (h2.y + h3.y));
    r.z = aL * (hl.z + bb.z) + aH * ((h0.z + h1.z) + (h2.z + h3.z));
    r.w = aL * (hl.w + bb.w) + aH * ((h0.w + h1.w) + (h2.w + h3.w));
    reinterpret_cast<float4*>(out)[id] = r;
}

// ---------------------------------------------------------------------------
extern "C" void kernel_launch(void* const* d_in, const int* in_sizes, int n_in,
                              void* d_out, int out_size)
{
    const float* x      = (const float*)d_in[0];
    const void*  ei_raw = d_in[1];
    const float* lap    = (const float*)d_in[2];
    const float* d_inv  = (const float*)d_in[3];
    const float* W_high = (const float*)d_in[4];
    const float* W_conv = (const float*)d_in[5];
    const float* b_conv = (const float*)d_in[6];
    const float* aL     = (const float*)d_in[7];
    const float* aH     = (const float*)d_in[8];
    float*       out    = (float*)d_out;

    float *pA, *pP0, *pP1, *pP2, *pP3;
    cudaGetSymbolAddress((void**)&pA,  g_A);
    cudaGetSymbolAddress((void**)&pP0, g_P0);
    cudaGetSymbolAddress((void**)&pP1, g_P1);
    cudaGetSymbolAddress((void**)&pP2, g_P2);
    cudaGetSymbolAddress((void**)&pP3, g_P3);
    __half* pXWh;
    cudaGetSymbolAddress((void**)&pXWh, g_XWh);
    __nv_bfloat16 *pDh, *pDl, *pLh, *pLl, *pBh, *pBl, *pXh, *pXl, *pWh, *pWl, *pWh2, *pWl2;
    cudaGetSymbolAddress((void**)&pDh, g_dinv_hi);
    cudaGetSymbolAddress((void**)&pDl, g_dinv_lo);
    cudaGetSymbolAddress((void**)&pLh, g_lap_hi);
    cudaGetSymbolAddress((void**)&pLl, g_lap_lo);
    cudaGetSymbolAddress((void**)&pBh, g_Bhi);
    cudaGetSymbolAddress((void**)&pBl, g_Blo);
    cudaGetSymbolAddress((void**)&pXh, g_xhi);
    cudaGetSymbolAddress((void**)&pXl, g_xlo);
    cudaGetSymbolAddress((void**)&pWh, g_Wth);
    cudaGetSymbolAddress((void**)&pWl, g_Wtl);
    cudaGetSymbolAddress((void**)&pWh2, g_Wth2);
    cudaGetSymbolAddress((void**)&pWl2, g_Wtl2);

    cudaFuncSetAttribute(gemm_mma_kernel<false, 0>, cudaFuncAttributeMaxDynamicSharedMemorySize, GEMM_SMEM);
    cudaFuncSetAttribute(gemm_mma_kernel<false, 1>, cudaFuncAttributeMaxDynamicSharedMemorySize, GEMM_SMEM);
    cudaFuncSetAttribute(gemm_mma_kernel<true,  2>, cudaFuncAttributeMaxDynamicSharedMemorySize, GEMM_SMEM);

    // Streams + events
    cudaStream_t s1, s2;
    cudaStreamCreateWithFlags(&s1, cudaStreamNonBlocking);
    cudaStreamCreateWithFlags(&s2, cudaStreamNonBlocking);
    cudaEvent_t E0, Ex, Ed, El, Eg;
    cudaEventCreateWithFlags(&E0, cudaEventDisableTiming);
    cudaEventCreateWithFlags(&Ex, cudaEventDisableTiming);
    cudaEventCreateWithFlags(&Ed, cudaEventDisableTiming);
    cudaEventCreateWithFlags(&El, cudaEventDisableTiming);
    cudaEventCreateWithFlags(&Eg, cudaEventDisableTiming);

    dim3 gBig(DIM / 128, N_NODES / 128, 4);    // (2, 32, 4)
    dim3 gRT (N_NODES / 128, DIM / 128, 1);    // (32, 2) : C = R^T [256 x 4096]
    dim3 gSm (DIM / 128, N_NODES / 128, 1);    // (2, 32) : XW_conv [4096 x 256]
    dim3 gTr(N_NODES / 32, DIM / 32);
    dim3 bTr(32, 8);
    dim3 gWt(DIM / 32, DIM / 32);
    const int NIT_BIG = (3 * N_NODES / 64) / 4;   // 48 per z
    const int NIT_SM  = 3 * DIM / 64;             // 12
    const int SEG_BIG = 6;
    const int SEG_SM  = 2;
    int nbig8 = N_NODES * N_NODES / 8;
    int nx8   = N_NODES * DIM / 8;

    // ---- fork ----
    cudaEventRecord(E0, 0);
    cudaStreamWaitEvent(s1, E0, 0);
    cudaStreamWaitEvent(s2, E0, 0);

    // s1: big matrix splits
    split_kernel<<<nbig8 / 256, 256, 0, s1>>>((const float4*)d_inv, (uint4*)pDh, (uint4*)pDl, nbig8);
    cudaEventRecord(Ed, s1);
    split_kernel<<<nbig8 / 256, 256, 0, s1>>>((const float4*)lap, (uint4*)pLh, (uint4*)pLl, nbig8);
    cudaEventRecord(El, s1);

    // s2: edge conversion + CSR + W_conv transpose; XW_conv GEMM; gather
    detect_init_kernel  <<<17, 256, 0, s2>>>((const unsigned int*)ei_raw);
    convert_edges_kernel<<<N_EDGES / 256, 256, 0, s2>>>(ei_raw);
    csr_scan_kernel     <<<1, 1024, 0, s2>>>();
    csr_place_kernel    <<<N_EDGES / 256, 256, 0, s2>>>();
    wtranspose_split_kernel<<<gWt, bTr, 0, s2>>>(W_conv, pWh2, pWl2);

    // s0: prologue — W_high^T splits + x splits
    wtranspose_split_kernel<<<gWt, bTr>>>(W_high, pWh, pWl);
    split_kernel<<<nx8 / 256, 256>>>((const float4*)x, (uint4*)pXh, (uint4*)pXl, nx8);
    cudaEventRecord(Ex, 0);

    // s2 continues: XW_conv = x @ W_conv (fp16 out), then gather into g_A
    cudaStreamWaitEvent(s2, Ex, 0);
    gemm_mma_kernel<false, 1><<<gSm, 128, GEMM_SMEM, s2>>>(pXh, pXl, pWh2, pWl2,
        nullptr, nullptr, nullptr, nullptr, pXWh, nullptr, nullptr,
        DIM, DIM, DIM, NIT_SM, SEG_SM);
    gather_kernel<<<N_NODES, 128, 0, s2>>>();
    cudaEventRecord(Eg, s2);

    // s0: R^T = relu(W_high^T @ x^T) with fused bf16-split epilogue -> Bhi/Blo
    gemm_mma_kernel<true, 2><<<gRT, 128, GEMM_SMEM>>>(pWh, pWl, pXh, pXl,
        nullptr, nullptr, nullptr, nullptr, nullptr, pBh, pBl,
        DIM, DIM, N_NODES, NIT_SM, SEG_SM);
    // T1 = d_inv @ R
    cudaStreamWaitEvent(0, Ed, 0);
    gemm_mma_kernel<false, 0><<<gBig, 128, GEMM_SMEM>>>(pDh, pDl, pBh, pBl,
        pP0, pP1, pP2, pP3, nullptr, nullptr, nullptr,
        N_NODES, N_NODES, DIM, NIT_BIG, SEG_BIG);
    // T2 = lap @ T1
    transpose_split_kernel<<<gTr, bTr>>>(pP0, pP1, pP2, pP3, pBh, pBl);
    cudaStreamWaitEvent(0, El, 0);
    gemm_mma_kernel<false, 0><<<gBig, 128, GEMM_SMEM>>>(pLh, pLl, pBh, pBl,
        pP0, pP1, pP2, pP3, nullptr, nullptr, nullptr,
        N_NODES, N_NODES, DIM, NIT_BIG, SEG_BIG);
    // Hh = d_inv @ T2
    transpose_split_kernel<<<gTr, bTr>>>(pP0, pP1, pP2, pP3, pBh, pBl);
    gemm_mma_kernel<false, 0><<<gBig, 128, GEMM_SMEM>>>(pDh, pDl, pBh, pBl,
        pP0, pP1, pP2, pP3, nullptr, nullptr, nullptr,
        N_NODES, N_NODES, DIM, NIT_BIG, SEG_BIG);

    // join: cheap combine
    cudaStreamWaitEvent(0, Eg, 0);
    int nvec = N_NODES * DIM / 4;
    combine_kernel<<<(nvec + 255) / 256, 256>>>(out, b_conv, aL, aH);

    cudaEventDestroy(E0); cudaEventDestroy(Ex); cudaEventDestroy(Ed);
    cudaEventDestroy(El); cudaEventDestroy(Eg);
    cudaStreamDestroy(s1); cudaStreamDestroy(s2);
}